// round 9
// baseline (speedup 1.0000x reference)
#include <cuda_runtime.h>

#define NN 4
#define BPTS 8192
#define CIN 32
#define DOUT 32
#define ANB 32
#define NBAS 36
#define TOTAL 32768
#define PPI 32
#define THREADS 512
#define WARPS 16
#define NITER (TOTAL/PPI)
#define KK 1152
#define KPW 72
#define MPS 33

typedef unsigned long long u64;

__device__ float g_inputT[NN*BPTS*CIN];   // (n,b,c)
__device__ float g_wlin[KK*32];           // [kk][d], kk=(s*4+r)*32+c

// ---------------- f32x2 helpers ----------------
__device__ __forceinline__ u64 pack2(float x, float y){
    u64 r; asm("mov.b64 %0,{%1,%2};" : "=l"(r) : "f"(x), "f"(y)); return r;
}
__device__ __forceinline__ void unpack2(u64 v, float& x, float& y){
    asm("mov.b64 {%0,%1},%2;" : "=f"(x), "=f"(y) : "l"(v));
}
__device__ __forceinline__ u64 fma2(u64 a, u64 b, u64 c){
    u64 d; asm("fma.rn.f32x2 %0,%1,%2,%3;" : "=l"(d) : "l"(a), "l"(b), "l"(c)); return d;
}
__device__ __forceinline__ u64 add2(u64 a, u64 b){
    u64 d; asm("add.rn.f32x2 %0,%1,%2;" : "=l"(d) : "l"(a), "l"(b)); return d;
}
__device__ __forceinline__ u64 mul2(u64 a, u64 b){
    u64 d; asm("mul.rn.f32x2 %0,%1,%2;" : "=l"(d) : "l"(a), "l"(b)); return d;
}
__device__ __forceinline__ float lds32(const float* p){
    float v; unsigned s = (unsigned)__cvta_generic_to_shared(p);
    asm volatile("ld.shared.f32 %0,[%1];" : "=f"(v) : "r"(s)); return v;
}
__device__ __forceinline__ void sts32(float* p, float v){
    unsigned s = (unsigned)__cvta_generic_to_shared(p);
    asm volatile("st.shared.f32 [%0],%1;" :: "r"(s), "f"(v));
}
__device__ __forceinline__ u64 lds64(const void* p){
    u64 v; unsigned s = (unsigned)__cvta_generic_to_shared(p);
    asm volatile("ld.shared.b64 %0,[%1];" : "=l"(v) : "r"(s)); return v;
}
__device__ __forceinline__ void sts64(void* p, u64 v){
    unsigned s = (unsigned)__cvta_generic_to_shared(p);
    asm volatile("st.shared.b64 [%0],%1;" :: "r"(s), "l"(v));
}

// ---------------- fused prep ----------------
__global__ void prep_all(const float* __restrict__ in, const float* __restrict__ W){
    const int bx = blockIdx.x;
    const int tid = threadIdx.x;           // 256
    if (bx < 1024){
        __shared__ float t[32][33];
        const int n  = bx >> 8;
        const int b0 = (bx & 255) * 32;
        const int tx = tid & 31, ty = tid >> 5;
        #pragma unroll
        for (int i = ty; i < 32; i += 8)
            t[i][tx] = in[(n*CIN + i)*BPTS + b0 + tx];
        __syncthreads();
        #pragma unroll
        for (int i = ty; i < 32; i += 8)
            g_inputT[(n*BPTS + b0 + i)*CIN + tx] = t[tx][i];
    } else {
        int t = (bx - 1024)*256 + tid;
        if (t < KK*32){
            int d  = t & 31;
            int kk = t >> 5;
            int c   = kk & 31;
            int s4r = kk >> 5;
            int r = s4r & 3, s = s4r >> 2;
            g_wlin[t] = W[(d*CIN + c)*NBAS + r*9 + s];
        }
    }
}

// ---------------- main ----------------
// smem:
//   geomP : 9 u64 fields x 512 rows  = 36864 B
//           fields 0..3 = (rb_r,rb_r) dup; 4..7 = (y0,y1)..(y6,y7); 8 = (y8,y8)
//   Mp    : KK*33 floats             = 152064 B
// total 188928 B. redd (16w*32l*17 u64) ALIASES Mp (barrier-ordered).
#define SM_GP   0
#define SM_MP   (9*512*2)                 // floats
#define SM_FLOATS (SM_MP + KK*MPS)

__global__ void __launch_bounds__(THREADS, 1)
se3_main(const float* __restrict__ coords,
         const float* __restrict__ rmask,
         const int*   __restrict__ nbrs,
         float*       __restrict__ out)
{
    extern __shared__ float smem[];
    u64*   geomP = (u64*)(smem + SM_GP);     // [q*512 + row]
    float* Mp    = smem + SM_MP;             // [kk*33 + p]
    u64*   redd  = (u64*)Mp;                 // alias, barrier-ordered

    const int tid  = threadIdx.x;
    const int w    = tid >> 5;               // 0..15
    const int lane = tid & 31;
    const int pg   = lane & 7;               // p-chunk (4 p each)
    const int dg   = lane >> 3;              // d-group (8 d each)

    for (int grp = blockIdx.x; grp < NITER; grp += gridDim.x) {
        const int flatbase = grp*PPI;
        const int n   = flatbase >> 13;
        const int bb0 = flatbase & (BPTS-1);

        // ================= Phase A: 2 points per warp =================
        #pragma unroll 1
        for (int sub = 0; sub < 2; sub++){
            const int p = w*2 + sub;
            const int flat = flatbase + p;

            // geometry, lane = neighbor a
            const int nb_idx = flat*ANB + lane;
            const int jn  = nbrs[nb_idx];
            const float msk = rmask[nb_idx];
            const float* cc = coords + (long)flat*3;
            const float c0x = cc[0], c0y = cc[1], c0z = cc[2];
            const float* cj = coords + ((long)(n*BPTS + jn))*3;
            const float dx = cj[0]-c0x, dy = cj[1]-c0y, dz = cj[2]-c0z;
            const float r  = sqrtf(dx*dx + dy*dy + dz*dz);
            const float inv = __fdividef(1.0f, r + 1e-8f);
            const float ux = dx*inv, uy = dy*inv, uz = dz*inv;
            const float y0 = 0.28209479f;
            const float y1 = 0.48860251f*ux, y2 = 0.48860251f*uy, y3 = 0.48860251f*uz;
            const float y4 = 1.09254843f*ux*uy, y5 = 1.09254843f*uy*uz;
            const float y6 = 0.31539157f*(3.0f*uz*uz - 1.0f);
            const float y7 = 1.09254843f*ux*uz;
            const float y8 = 0.54627421f*(ux*ux - uy*uy);
            float rb0, rb1, rb2, rb3;
            {
                float t0 = (r - 0.5f)*2.0f, t1 = (r - 1.0f)*2.0f;
                float t2 = (r - 1.5f)*2.0f, t3 = (r - 2.0f)*2.0f;
                rb0 = msk*__expf(-t0*t0); rb1 = msk*__expf(-t1*t1);
                rb2 = msk*__expf(-t2*t2); rb3 = msk*__expf(-t3*t3);
            }
            // SoA fields, lane-distinct stride-1 => conflict-free sts64
            const int row = w*32 + lane;
            sts64(geomP + 0*512 + row, pack2(rb0, rb0));
            sts64(geomP + 1*512 + row, pack2(rb1, rb1));
            sts64(geomP + 2*512 + row, pack2(rb2, rb2));
            sts64(geomP + 3*512 + row, pack2(rb3, rb3));
            sts64(geomP + 4*512 + row, pack2(y0, y1));
            sts64(geomP + 5*512 + row, pack2(y2, y3));
            sts64(geomP + 6*512 + row, pack2(y4, y5));
            sts64(geomP + 7*512 + row, pack2(y6, y7));
            sts64(geomP + 8*512 + row, pack2(y8, y8));
            __syncwarp();

            // feature gather (lane = channel c), prefetch depth 4
            const float* inrow = g_inputT + (((long)n << 13) * CIN) + lane;
            float fp[4];
            #pragma unroll
            for (int q = 0; q < 4; q++){
                int jq = __shfl_sync(0xffffffffu, jn, q);
                fp[q] = __ldg(inrow + (long)jq*CIN);
            }
            // accumulators: M[r][j] = (M[s=2j][r], M[s=2j+1][r]); j=4 lo = M[s=8][r]
            u64 M[4][5];
            #pragma unroll
            for (int r4 = 0; r4 < 4; r4++)
                #pragma unroll
                for (int jj = 0; jj < 5; jj++) M[r4][jj] = 0ull;

            #pragma unroll
            for (int a4 = 0; a4 < 32; a4 += 4){
                #pragma unroll
                for (int q = 0; q < 4; q++){
                    const int a = a4 + q;
                    const int row2 = w*32 + a;
                    const float f = fp[q];
                    if (a4 + 4 < 32){
                        int jq = __shfl_sync(0xffffffffu, jn, a + 4);
                        fp[q] = __ldg(inrow + (long)jq*CIN);
                    }
                    u64 f2 = pack2(f, f);
                    u64 yv0 = lds64(geomP + 4*512 + row2);
                    u64 yv1 = lds64(geomP + 5*512 + row2);
                    u64 yv2 = lds64(geomP + 6*512 + row2);
                    u64 yv3 = lds64(geomP + 7*512 + row2);
                    u64 yv4 = lds64(geomP + 8*512 + row2);
                    // rb fields loaded just before use -> low liveness
                    u64 fr0 = mul2(f2, lds64(geomP + 0*512 + row2));
                    M[0][0]=fma2(fr0,yv0,M[0][0]); M[0][1]=fma2(fr0,yv1,M[0][1]);
                    M[0][2]=fma2(fr0,yv2,M[0][2]); M[0][3]=fma2(fr0,yv3,M[0][3]);
                    M[0][4]=fma2(fr0,yv4,M[0][4]);
                    u64 fr1 = mul2(f2, lds64(geomP + 1*512 + row2));
                    M[1][0]=fma2(fr1,yv0,M[1][0]); M[1][1]=fma2(fr1,yv1,M[1][1]);
                    M[1][2]=fma2(fr1,yv2,M[1][2]); M[1][3]=fma2(fr1,yv3,M[1][3]);
                    M[1][4]=fma2(fr1,yv4,M[1][4]);
                    u64 fr2 = mul2(f2, lds64(geomP + 2*512 + row2));
                    M[2][0]=fma2(fr2,yv0,M[2][0]); M[2][1]=fma2(fr2,yv1,M[2][1]);
                    M[2][2]=fma2(fr2,yv2,M[2][2]); M[2][3]=fma2(fr2,yv3,M[2][3]);
                    M[2][4]=fma2(fr2,yv4,M[2][4]);
                    u64 fr3 = mul2(f2, lds64(geomP + 3*512 + row2));
                    M[3][0]=fma2(fr3,yv0,M[3][0]); M[3][1]=fma2(fr3,yv1,M[3][1]);
                    M[3][2]=fma2(fr3,yv2,M[3][2]); M[3][3]=fma2(fr3,yv3,M[3][3]);
                    M[3][4]=fma2(fr3,yv4,M[3][4]);
                }
            }
            // Mp[kk][p], kk=(s*4+r)*32+c(=lane): conflict-free scalar stores
            #pragma unroll
            for (int r4 = 0; r4 < 4; r4++){
                #pragma unroll
                for (int jj = 0; jj < 4; jj++){
                    float alo, ahi;
                    unpack2(M[r4][jj], alo, ahi);
                    sts32(Mp + (((2*jj  )*4 + r4)*32 + lane)*MPS + p, alo);
                    sts32(Mp + (((2*jj+1)*4 + r4)*32 + lane)*MPS + p, ahi);
                }
                float alo, ahi;
                unpack2(M[r4][4], alo, ahi);
                sts32(Mp + ((8*4 + r4)*32 + lane)*MPS + p, alo);
            }
            __syncwarp();
        }
        __syncthreads();   // Mp complete

        // ================= Phase B: k-split GEMM, d-paired =================
        u64 acc[4][4];     // [pi][dd]  d-pair = (dg*8+dd*2, +1)
        #pragma unroll
        for (int a = 0; a < 4; a++)
            #pragma unroll
            for (int b = 0; b < 4; b++) acc[a][b] = 0ull;

        const int kb = w*KPW;
        const ulonglong2* wq = ((const ulonglong2*)g_wlin) + dg*2;  // + k*8 (+1)
        ulonglong2 pf0[2], pf1[2];
        #pragma unroll
        for (int i = 0; i < 2; i++){
            pf0[i] = __ldg(wq + (long)(kb+i)*8);
            pf1[i] = __ldg(wq + (long)(kb+i)*8 + 1);
        }
        #pragma unroll 2
        for (int kk = 0; kk < KPW; kk++){
            const int k = kb + kk;
            const int slot = kk & 1;
            const ulonglong2 wa = pf0[slot];
            const ulonglong2 wb = pf1[slot];
            if (kk + 2 < KPW){
                pf0[slot] = __ldg(wq + (long)(k+2)*8);
                pf1[slot] = __ldg(wq + (long)(k+2)*8 + 1);
            }
            const float* mr = Mp + k*MPS + pg*4;
            float m0 = lds32(mr+0), m1 = lds32(mr+1);
            float m2 = lds32(mr+2), m3 = lds32(mr+3);
            u64 md0 = pack2(m0,m0), md1 = pack2(m1,m1);
            u64 md2 = pack2(m2,m2), md3 = pack2(m3,m3);
            acc[0][0]=fma2(md0, wa.x, acc[0][0]);
            acc[0][1]=fma2(md0, wa.y, acc[0][1]);
            acc[0][2]=fma2(md0, wb.x, acc[0][2]);
            acc[0][3]=fma2(md0, wb.y, acc[0][3]);
            acc[1][0]=fma2(md1, wa.x, acc[1][0]);
            acc[1][1]=fma2(md1, wa.y, acc[1][1]);
            acc[1][2]=fma2(md1, wb.x, acc[1][2]);
            acc[1][3]=fma2(md1, wb.y, acc[1][3]);
            acc[2][0]=fma2(md2, wa.x, acc[2][0]);
            acc[2][1]=fma2(md2, wa.y, acc[2][1]);
            acc[2][2]=fma2(md2, wb.x, acc[2][2]);
            acc[2][3]=fma2(md2, wb.y, acc[2][3]);
            acc[3][0]=fma2(md3, wa.x, acc[3][0]);
            acc[3][1]=fma2(md3, wa.y, acc[3][1]);
            acc[3][2]=fma2(md3, wb.x, acc[3][2]);
            acc[3][3]=fma2(md3, wb.y, acc[3][3]);
        }
        __syncthreads();   // all Mp reads done before redd (alias) writes

        // partial store: per-thread slot, pad 17 u64 -> conflict-free
        {
            u64* slotp = redd + (u64)(w*32 + lane)*17;
            #pragma unroll
            for (int pi = 0; pi < 4; pi++)
                #pragma unroll
                for (int dd = 0; dd < 4; dd++)
                    sts64(slotp + pi*4 + dd, acc[pi][dd]);
        }
        __syncthreads();

        // reduce 16 k-slices
        {
            const int rw = tid >> 5;           // 0..15 = pi*4+dd
            const int rl = tid & 31;           // producer lane
            const int pi = rw >> 2, dd = rw & 3;
            const int dgp = rl >> 3, pgp = rl & 7;
            const u64* base = redd + rl*17 + rw;
            u64 s = lds64(base);
            #pragma unroll
            for (int ks = 1; ks < 16; ks++)
                s = add2(s, lds64(base + ks*544));
            float lo, hi; unpack2(s, lo, hi);
            const int p = pgp*4 + pi;
            const int d = dgp*8 + dd*2;
            float* o = out + ((long)(n*DOUT + d))*BPTS + bb0 + p;
            o[0]    = lo;
            o[BPTS] = hi;
        }
        __syncthreads();   // protect redd (=Mp) before next iter's Phase A
    }
}

// ---------------- launch ----------------
extern "C" void kernel_launch(void* const* d_in, const int* in_sizes, int n_in,
                              void* d_out, int out_size)
{
    const float* input  = (const float*)d_in[0];
    const float* coords = (const float*)d_in[1];
    const float* rmask  = (const float*)d_in[2];
    const float* W      = (const float*)d_in[3];
    const int*   nbrs   = (const int*)d_in[4];
    float* out = (float*)d_out;

    (void)in_sizes; (void)n_in; (void)out_size;

    prep_all<<<1168, 256>>>(input, W);

    int dev = 0; cudaGetDevice(&dev);
    int smcount = 148;
    cudaDeviceGetAttribute(&smcount, cudaDevAttrMultiProcessorCount, dev);

    size_t shmem = (size_t)SM_FLOATS * sizeof(float);   // 188928 B
    cudaFuncSetAttribute(se3_main, cudaFuncAttributeMaxDynamicSharedMemorySize, (int)shmem);
    se3_main<<<smcount, THREADS, shmem>>>(coords, rmask, nbrs, out);
}

// round 10
// speedup vs baseline: 1.0698x; 1.0698x over previous
#include <cuda_runtime.h>

#define NN 4
#define BPTS 8192
#define CIN 32
#define DOUT 32
#define ANB 32
#define NBAS 36
#define TOTAL 32768
#define PPI 16              // points per CTA iteration
#define THREADS 256
#define WARPS 8
#define NITER (TOTAL/PPI)   // 2048
#define KK 1152
#define KPW 144             // k per warp (8 warps)
#define MPS 17              // Mp row stride (16 p + pad)

typedef unsigned long long u64;

__device__ float g_inputT[NN*BPTS*CIN];   // (n,b,c)
__device__ float g_wlin[KK*32];           // [kk][d], kk=(s*4+r)*32+c

// ---------------- f32x2 helpers ----------------
__device__ __forceinline__ u64 pack2(float x, float y){
    u64 r; asm("mov.b64 %0,{%1,%2};" : "=l"(r) : "f"(x), "f"(y)); return r;
}
__device__ __forceinline__ void unpack2(u64 v, float& x, float& y){
    asm("mov.b64 {%0,%1},%2;" : "=f"(x), "=f"(y) : "l"(v));
}
__device__ __forceinline__ u64 fma2(u64 a, u64 b, u64 c){
    u64 d; asm("fma.rn.f32x2 %0,%1,%2,%3;" : "=l"(d) : "l"(a), "l"(b), "l"(c)); return d;
}
__device__ __forceinline__ u64 add2(u64 a, u64 b){
    u64 d; asm("add.rn.f32x2 %0,%1,%2;" : "=l"(d) : "l"(a), "l"(b)); return d;
}
__device__ __forceinline__ u64 mul2(u64 a, u64 b){
    u64 d; asm("mul.rn.f32x2 %0,%1,%2;" : "=l"(d) : "l"(a), "l"(b)); return d;
}
__device__ __forceinline__ float lds32(const float* p){
    float v; unsigned s = (unsigned)__cvta_generic_to_shared(p);
    asm volatile("ld.shared.f32 %0,[%1];" : "=f"(v) : "r"(s)); return v;
}
__device__ __forceinline__ void sts32(float* p, float v){
    unsigned s = (unsigned)__cvta_generic_to_shared(p);
    asm volatile("st.shared.f32 [%0],%1;" :: "r"(s), "f"(v));
}
__device__ __forceinline__ u64 lds64(const void* p){
    u64 v; unsigned s = (unsigned)__cvta_generic_to_shared(p);
    asm volatile("ld.shared.b64 %0,[%1];" : "=l"(v) : "r"(s)); return v;
}
__device__ __forceinline__ void sts64(void* p, u64 v){
    unsigned s = (unsigned)__cvta_generic_to_shared(p);
    asm volatile("st.shared.b64 [%0],%1;" :: "r"(s), "l"(v));
}

// ---------------- fused prep ----------------
__global__ void prep_all(const float* __restrict__ in, const float* __restrict__ W){
    const int bx = blockIdx.x;
    const int tid = threadIdx.x;           // 256
    if (bx < 1024){
        __shared__ float t[32][33];
        const int n  = bx >> 8;
        const int b0 = (bx & 255) * 32;
        const int tx = tid & 31, ty = tid >> 5;
        #pragma unroll
        for (int i = ty; i < 32; i += 8)
            t[i][tx] = in[(n*CIN + i)*BPTS + b0 + tx];
        __syncthreads();
        #pragma unroll
        for (int i = ty; i < 32; i += 8)
            g_inputT[(n*BPTS + b0 + i)*CIN + tx] = t[tx][i];
    } else {
        int t = (bx - 1024)*256 + tid;
        if (t < KK*32){
            int d  = t & 31;
            int kk = t >> 5;
            int c   = kk & 31;
            int s4r = kk >> 5;
            int r = s4r & 3, s = s4r >> 2;
            g_wlin[t] = W[(d*CIN + c)*NBAS + r*9 + s];
        }
    }
}

// ---------------- main ----------------
// smem floats (per CTA):
//   geomP : 6 u64 fields x 256 rows = 3072 f  (rb01,rb23,y01,y23,y45,y67)
//   geomY8: 256 f
//   Mp    : KK*17 = 19584 f
// total 22912 f = 91648 B; 2 CTAs/SM. redd (8w*32l*17 u64 = 34816 B) ALIASES Mp.
#define SM_GP   0
#define SM_Y8   3072
#define SM_MP   (3072 + 256)
#define SM_FLOATS (SM_MP + KK*MPS)

__global__ void __launch_bounds__(THREADS, 2)
se3_main(const float* __restrict__ coords,
         const float* __restrict__ rmask,
         const int*   __restrict__ nbrs,
         float*       __restrict__ out)
{
    extern __shared__ float smem[];
    u64*   geomP  = (u64*)(smem + SM_GP);    // [q*256 + row]
    float* geomY8 = smem + SM_Y8;            // [row]
    float* Mp     = smem + SM_MP;            // [kk*17 + p]
    u64*   redd   = (u64*)Mp;                // alias, barrier-ordered

    const int tid  = threadIdx.x;
    const int w    = tid >> 5;               // 0..7
    const int lane = tid & 31;
    const int pg   = lane & 7;               // p-chunk (2 p each)
    const int dg   = lane >> 3;              // d-group (8 d each)

    for (int grp = blockIdx.x; grp < NITER; grp += gridDim.x) {
        const int flatbase = grp*PPI;
        const int n   = flatbase >> 13;
        const int bb0 = flatbase & (BPTS-1);

        // ================= Phase A: 2 points per warp (R7-identical math) =====
        #pragma unroll 1
        for (int sub = 0; sub < 2; sub++){
            const int p = w*2 + sub;
            const int flat = flatbase + p;

            const int nb_idx = flat*ANB + lane;
            const int jn  = nbrs[nb_idx];
            const float msk = rmask[nb_idx];
            const float* cc = coords + (long)flat*3;
            const float c0x = cc[0], c0y = cc[1], c0z = cc[2];
            const float* cj = coords + ((long)(n*BPTS + jn))*3;
            const float dx = cj[0]-c0x, dy = cj[1]-c0y, dz = cj[2]-c0z;
            const float r  = sqrtf(dx*dx + dy*dy + dz*dz);
            const float inv = __fdividef(1.0f, r + 1e-8f);
            const float ux = dx*inv, uy = dy*inv, uz = dz*inv;
            const float y0 = 0.28209479f;
            const float y1 = 0.48860251f*ux, y2 = 0.48860251f*uy, y3 = 0.48860251f*uz;
            const float y4 = 1.09254843f*ux*uy, y5 = 1.09254843f*uy*uz;
            const float y6 = 0.31539157f*(3.0f*uz*uz - 1.0f);
            const float y7 = 1.09254843f*ux*uz;
            const float y8 = 0.54627421f*(ux*ux - uy*uy);
            float rb0, rb1, rb2, rb3;
            {
                float t0 = (r - 0.5f)*2.0f, t1 = (r - 1.0f)*2.0f;
                float t2 = (r - 1.5f)*2.0f, t3 = (r - 2.0f)*2.0f;
                rb0 = msk*__expf(-t0*t0); rb1 = msk*__expf(-t1*t1);
                rb2 = msk*__expf(-t2*t2); rb3 = msk*__expf(-t3*t3);
            }
            const int row = w*32 + lane;
            sts64(geomP + 0*256 + row, pack2(rb0, rb1));
            sts64(geomP + 1*256 + row, pack2(rb2, rb3));
            sts64(geomP + 2*256 + row, pack2(y0, y1));
            sts64(geomP + 3*256 + row, pack2(y2, y3));
            sts64(geomP + 4*256 + row, pack2(y4, y5));
            sts64(geomP + 5*256 + row, pack2(y6, y7));
            sts32(geomY8 + row, y8);
            __syncwarp();

            // feature gather (lane = channel c), prefetch depth 8
            const float* inrow = g_inputT + (((long)n << 13) * CIN) + lane;
            float fp[8];
            #pragma unroll
            for (int q = 0; q < 8; q++){
                int jq = __shfl_sync(0xffffffffu, jn, q);
                fp[q] = __ldg(inrow + (long)jq*CIN);
            }
            u64 M01[9], M23[9];
            #pragma unroll
            for (int s = 0; s < 9; s++){ M01[s] = 0ull; M23[s] = 0ull; }

            #pragma unroll
            for (int a8 = 0; a8 < 32; a8 += 8){
                #pragma unroll
                for (int q = 0; q < 8; q++){
                    const int a = a8 + q;
                    const int row2 = w*32 + a;
                    u64 rb01 = lds64(geomP + 0*256 + row2);
                    u64 rb23 = lds64(geomP + 1*256 + row2);
                    u64 y01  = lds64(geomP + 2*256 + row2);
                    u64 y23  = lds64(geomP + 3*256 + row2);
                    u64 y45  = lds64(geomP + 4*256 + row2);
                    u64 y67  = lds64(geomP + 5*256 + row2);
                    float y8v = lds32(geomY8 + row2);
                    const float f = fp[q];
                    if (a8 + 8 < 32){
                        int jq = __shfl_sync(0xffffffffu, jn, a + 8);
                        fp[q] = __ldg(inrow + (long)jq*CIN);
                    }
                    u64 f2 = pack2(f, f);
                    u64 frb01 = mul2(f2, rb01);
                    u64 frb23 = mul2(f2, rb23);
                    float t0,t1,t2,t3,t4,t5,t6,t7;
                    unpack2(y01, t0, t1); unpack2(y23, t2, t3);
                    unpack2(y45, t4, t5); unpack2(y67, t6, t7);
                    u64 yd[9];
                    yd[0]=pack2(t0,t0); yd[1]=pack2(t1,t1); yd[2]=pack2(t2,t2);
                    yd[3]=pack2(t3,t3); yd[4]=pack2(t4,t4); yd[5]=pack2(t5,t5);
                    yd[6]=pack2(t6,t6); yd[7]=pack2(t7,t7); yd[8]=pack2(y8v,y8v);
                    #pragma unroll
                    for (int s = 0; s < 9; s++){
                        M01[s] = fma2(frb01, yd[s], M01[s]);
                        M23[s] = fma2(frb23, yd[s], M23[s]);
                    }
                }
            }
            // Mp[kk][p], kk=(s*4+r)*32+c(=lane): conflict-free scalar stores
            #pragma unroll
            for (int s = 0; s < 9; s++){
                float a0,a1,a2,a3;
                unpack2(M01[s], a0, a1);
                unpack2(M23[s], a2, a3);
                float* base = Mp + ((s*4)*32 + lane)*MPS + p;
                sts32(base + 0*32*MPS, a0);
                sts32(base + 1*32*MPS, a1);
                sts32(base + 2*32*MPS, a2);
                sts32(base + 3*32*MPS, a3);
            }
            __syncwarp();
        }
        __syncthreads();   // Mp complete

        // ================= Phase B: k-split GEMM, 2p x 8d tile =================
        u64 acc[2][4];     // [pi][dd]  d-pair = (dg*8+dd*2, +1)
        #pragma unroll
        for (int a = 0; a < 2; a++)
            #pragma unroll
            for (int b = 0; b < 4; b++) acc[a][b] = 0ull;

        const int kb = w*KPW;
        const ulonglong2* wq = ((const ulonglong2*)g_wlin) + dg*2;  // + k*8 (+1)
        ulonglong2 pf0[3], pf1[3];
        #pragma unroll
        for (int i = 0; i < 3; i++){
            pf0[i] = __ldg(wq + (long)(kb+i)*8);
            pf1[i] = __ldg(wq + (long)(kb+i)*8 + 1);
        }
        #pragma unroll 3
        for (int kk = 0; kk < KPW; kk++){
            const int k = kb + kk;
            const int slot = kk % 3;
            const ulonglong2 wa = pf0[slot];
            const ulonglong2 wb = pf1[slot];
            if (kk + 3 < KPW){
                pf0[slot] = __ldg(wq + (long)(k+3)*8);
                pf1[slot] = __ldg(wq + (long)(k+3)*8 + 1);
            }
            const float* mr = Mp + k*MPS + pg*2;
            float m0 = lds32(mr+0), m1 = lds32(mr+1);
            u64 md0 = pack2(m0,m0), md1 = pack2(m1,m1);
            acc[0][0]=fma2(md0, wa.x, acc[0][0]);
            acc[0][1]=fma2(md0, wa.y, acc[0][1]);
            acc[0][2]=fma2(md0, wb.x, acc[0][2]);
            acc[0][3]=fma2(md0, wb.y, acc[0][3]);
            acc[1][0]=fma2(md1, wa.x, acc[1][0]);
            acc[1][1]=fma2(md1, wa.y, acc[1][1]);
            acc[1][2]=fma2(md1, wb.x, acc[1][2]);
            acc[1][3]=fma2(md1, wb.y, acc[1][3]);
        }
        __syncthreads();   // all Mp reads done before redd (alias) writes

        // partial store: per-thread slot, pad 17 u64
        {
            u64* slotp = redd + (u64)(w*32 + lane)*17;
            #pragma unroll
            for (int pi = 0; pi < 2; pi++)
                #pragma unroll
                for (int dd = 0; dd < 4; dd++)
                    sts64(slotp + pi*4 + dd, acc[pi][dd]);
        }
        __syncthreads();

        // reduce 8 k-slices: thread -> (slot rw = pi*4+dd, producer lane rl)
        {
            const int rw = tid >> 5;           // 0..7 = pi*4+dd
            const int rl = tid & 31;
            const int pi = rw >> 2, dd = rw & 3;
            const int dgp = rl >> 3, pgp = rl & 7;
            const u64* base = redd + rl*17 + rw;
            u64 s = lds64(base);
            #pragma unroll
            for (int ks = 1; ks < 8; ks++)
                s = add2(s, lds64(base + ks*(32*17)));
            float lo, hi; unpack2(s, lo, hi);
            const int p = pgp*2 + pi;
            const int d = dgp*8 + dd*2;
            float* o = out + ((long)(n*DOUT + d))*BPTS + bb0 + p;
            o[0]    = lo;
            o[BPTS] = hi;
        }
        __syncthreads();   // protect redd (=Mp) before next iter's Phase A
    }
}

// ---------------- launch ----------------
extern "C" void kernel_launch(void* const* d_in, const int* in_sizes, int n_in,
                              void* d_out, int out_size)
{
    const float* input  = (const float*)d_in[0];
    const float* coords = (const float*)d_in[1];
    const float* rmask  = (const float*)d_in[2];
    const float* W      = (const float*)d_in[3];
    const int*   nbrs   = (const int*)d_in[4];
    float* out = (float*)d_out;

    (void)in_sizes; (void)n_in; (void)out_size;

    prep_all<<<1168, 256>>>(input, W);

    int dev = 0; cudaGetDevice(&dev);
    int smcount = 148;
    cudaDeviceGetAttribute(&smcount, cudaDevAttrMultiProcessorCount, dev);

    size_t shmem = (size_t)SM_FLOATS * sizeof(float);   // 91648 B per CTA
    cudaFuncSetAttribute(se3_main, cudaFuncAttributeMaxDynamicSharedMemorySize, (int)shmem);
    se3_main<<<2*smcount, THREADS, shmem>>>(coords, rmask, nbrs, out);
}

// round 11
// speedup vs baseline: 1.2427x; 1.1617x over previous
#include <cuda_runtime.h>

#define NN 4
#define BPTS 8192
#define CIN 32
#define DOUT 32
#define ANB 32
#define NBAS 36
#define TOTAL 32768
#define PPI 32
#define THREADS 512
#define WARPS 16
#define NITER (TOTAL/PPI)
#define KK 1152
#define KPW 72
#define MPS 34              // even -> lds64-aligned M rows

typedef unsigned long long u64;

__device__ float g_inputT[NN*BPTS*CIN];   // (n,b,c)
__device__ float g_wlin[KK*32];           // [kk][d], kk=(s*4+r)*32+c

// ---------------- f32x2 helpers ----------------
__device__ __forceinline__ u64 pack2(float x, float y){
    u64 r; asm("mov.b64 %0,{%1,%2};" : "=l"(r) : "f"(x), "f"(y)); return r;
}
__device__ __forceinline__ void unpack2(u64 v, float& x, float& y){
    asm("mov.b64 {%0,%1},%2;" : "=f"(x), "=f"(y) : "l"(v));
}
__device__ __forceinline__ u64 swap2(u64 v){
    float a, b; unpack2(v, a, b); return pack2(b, a);
}
__device__ __forceinline__ u64 fma2(u64 a, u64 b, u64 c){
    u64 d; asm("fma.rn.f32x2 %0,%1,%2,%3;" : "=l"(d) : "l"(a), "l"(b), "l"(c)); return d;
}
__device__ __forceinline__ u64 add2(u64 a, u64 b){
    u64 d; asm("add.rn.f32x2 %0,%1,%2;" : "=l"(d) : "l"(a), "l"(b)); return d;
}
__device__ __forceinline__ u64 mul2(u64 a, u64 b){
    u64 d; asm("mul.rn.f32x2 %0,%1,%2;" : "=l"(d) : "l"(a), "l"(b)); return d;
}
__device__ __forceinline__ float lds32(const float* p){
    float v; unsigned s = (unsigned)__cvta_generic_to_shared(p);
    asm volatile("ld.shared.f32 %0,[%1];" : "=f"(v) : "r"(s)); return v;
}
__device__ __forceinline__ void sts32(float* p, float v){
    unsigned s = (unsigned)__cvta_generic_to_shared(p);
    asm volatile("st.shared.f32 [%0],%1;" :: "r"(s), "f"(v));
}
__device__ __forceinline__ u64 lds64(const void* p){
    u64 v; unsigned s = (unsigned)__cvta_generic_to_shared(p);
    asm volatile("ld.shared.b64 %0,[%1];" : "=l"(v) : "r"(s)); return v;
}
__device__ __forceinline__ void sts64(void* p, u64 v){
    unsigned s = (unsigned)__cvta_generic_to_shared(p);
    asm volatile("st.shared.b64 [%0],%1;" :: "r"(s), "l"(v));
}

// ---------------- fused prep ----------------
__global__ void prep_all(const float* __restrict__ in, const float* __restrict__ W){
    const int bx = blockIdx.x;
    const int tid = threadIdx.x;           // 256
    if (bx < 1024){
        __shared__ float t[32][33];
        const int n  = bx >> 8;
        const int b0 = (bx & 255) * 32;
        const int tx = tid & 31, ty = tid >> 5;
        #pragma unroll
        for (int i = ty; i < 32; i += 8)
            t[i][tx] = in[(n*CIN + i)*BPTS + b0 + tx];
        __syncthreads();
        #pragma unroll
        for (int i = ty; i < 32; i += 8)
            g_inputT[(n*BPTS + b0 + i)*CIN + tx] = t[tx][i];
    } else {
        int t = (bx - 1024)*256 + tid;
        if (t < KK*32){
            int d  = t & 31;
            int kk = t >> 5;
            int c   = kk & 31;
            int s4r = kk >> 5;
            int r = s4r & 3, s = s4r >> 2;
            g_wlin[t] = W[(d*CIN + c)*NBAS + r*9 + s];
        }
    }
}

// ---------------- main ----------------
// smem floats:
//   geomP : 6 u64 fields x 512 rows = 6144  (rb01,rb23,(y0,y1),(y2,y3),(y4,y5),(y6,y7))
//   geomY8: 512
//   Mp    : KK*34 = 39168
// total 45824 f = 183296 B. redd (16w*32l*17 u64) ALIASES Mp (barrier-ordered).
#define SM_GP   0
#define SM_Y8   6144
#define SM_MP   (6144 + 512)
#define SM_FLOATS (SM_MP + KK*MPS)

__global__ void __launch_bounds__(THREADS, 1)
se3_main(const float* __restrict__ coords,
         const float* __restrict__ rmask,
         const int*   __restrict__ nbrs,
         float*       __restrict__ out)
{
    extern __shared__ float smem[];
    u64*   geomP  = (u64*)(smem + SM_GP);    // [q*512 + row]
    float* geomY8 = smem + SM_Y8;            // [row]
    float* Mp     = smem + SM_MP;            // [kk*34 + p]
    u64*   redd   = (u64*)Mp;                // alias, barrier-ordered

    const int tid  = threadIdx.x;
    const int w    = tid >> 5;               // 0..15
    const int lane = tid & 31;
    const int pg   = lane & 7;               // p-chunk (4 p each)
    const int dg   = lane >> 3;              // d-group (8 d each)

    for (int grp = blockIdx.x; grp < NITER; grp += gridDim.x) {
        const int flatbase = grp*PPI;
        const int n   = flatbase >> 13;
        const int bb0 = flatbase & (BPTS-1);

        // ================= Phase A: 2 points per warp =================
        #pragma unroll 1
        for (int sub = 0; sub < 2; sub++){
            const int p = w*2 + sub;
            const int flat = flatbase + p;

            // geometry, lane = neighbor a
            const int nb_idx = flat*ANB + lane;
            const int jn  = nbrs[nb_idx];
            const float msk = rmask[nb_idx];
            const float* cc = coords + (long)flat*3;
            const float c0x = cc[0], c0y = cc[1], c0z = cc[2];
            const float* cj = coords + ((long)(n*BPTS + jn))*3;
            const float dx = cj[0]-c0x, dy = cj[1]-c0y, dz = cj[2]-c0z;
            const float r  = sqrtf(dx*dx + dy*dy + dz*dz);
            const float inv = __fdividef(1.0f, r + 1e-8f);
            const float ux = dx*inv, uy = dy*inv, uz = dz*inv;
            const float y0 = 0.28209479f;
            const float y1 = 0.48860251f*ux, y2 = 0.48860251f*uy, y3 = 0.48860251f*uz;
            const float y4 = 1.09254843f*ux*uy, y5 = 1.09254843f*uy*uz;
            const float y6 = 0.31539157f*(3.0f*uz*uz - 1.0f);
            const float y7 = 1.09254843f*ux*uz;
            const float y8 = 0.54627421f*(ux*ux - uy*uy);
            float rb0, rb1, rb2, rb3;
            {
                float t0 = (r - 0.5f)*2.0f, t1 = (r - 1.0f)*2.0f;
                float t2 = (r - 1.5f)*2.0f, t3 = (r - 2.0f)*2.0f;
                rb0 = msk*__expf(-t0*t0); rb1 = msk*__expf(-t1*t1);
                rb2 = msk*__expf(-t2*t2); rb3 = msk*__expf(-t3*t3);
            }
            const int row = w*32 + lane;
            sts64(geomP + 0*512 + row, pack2(rb0, rb1));
            sts64(geomP + 1*512 + row, pack2(rb2, rb3));
            sts64(geomP + 2*512 + row, pack2(y0, y1));
            sts64(geomP + 3*512 + row, pack2(y2, y3));
            sts64(geomP + 4*512 + row, pack2(y4, y5));
            sts64(geomP + 5*512 + row, pack2(y6, y7));
            sts32(geomY8 + row, y8);
            __syncwarp();

            // feature gather (lane = channel c), prefetch depth 8
            const float* inrow = g_inputT + (((long)n << 13) * CIN) + lane;
            float fp[8];
            #pragma unroll
            for (int q = 0; q < 8; q++){
                int jq = __shfl_sync(0xffffffffu, jn, q);
                fp[q] = __ldg(inrow + (long)jq*CIN);
            }
            // swap-pair accumulators:
            // A01[j]=(M[r0][2j],M[r1][2j+1]) B01[j]=(M[r1][2j],M[r0][2j+1])
            // A23/B23 same with (r2,r3); C01=(M[r0][8],M[r1][8]) C23=(M[r2][8],M[r3][8])
            u64 A01[4], B01[4], A23[4], B23[4], C01 = 0ull, C23 = 0ull;
            #pragma unroll
            for (int j = 0; j < 4; j++){ A01[j]=0ull; B01[j]=0ull; A23[j]=0ull; B23[j]=0ull; }

            #pragma unroll
            for (int a8 = 0; a8 < 32; a8 += 8){
                #pragma unroll
                for (int q = 0; q < 8; q++){
                    const int a = a8 + q;
                    const int row2 = w*32 + a;
                    u64 rb01 = lds64(geomP + 0*512 + row2);
                    u64 rb23 = lds64(geomP + 1*512 + row2);
                    u64 Y0 = lds64(geomP + 2*512 + row2);
                    u64 Y1 = lds64(geomP + 3*512 + row2);
                    u64 Y2 = lds64(geomP + 4*512 + row2);
                    u64 Y3 = lds64(geomP + 5*512 + row2);
                    float y8v = lds32(geomY8 + row2);
                    const float f = fp[q];
                    if (a8 + 8 < 32){
                        int jq = __shfl_sync(0xffffffffu, jn, a + 8);
                        fp[q] = __ldg(inrow + (long)jq*CIN);
                    }
                    u64 f2  = pack2(f, f);
                    u64 G01 = mul2(f2, rb01);     // (g0,g1)
                    u64 G23 = mul2(f2, rb23);     // (g2,g3)
                    u64 G10 = swap2(G01);
                    u64 G32 = swap2(G23);
                    u64 y8d = pack2(y8v, y8v);
                    A01[0]=fma2(G01,Y0,A01[0]); B01[0]=fma2(G10,Y0,B01[0]);
                    A23[0]=fma2(G23,Y0,A23[0]); B23[0]=fma2(G32,Y0,B23[0]);
                    A01[1]=fma2(G01,Y1,A01[1]); B01[1]=fma2(G10,Y1,B01[1]);
                    A23[1]=fma2(G23,Y1,A23[1]); B23[1]=fma2(G32,Y1,B23[1]);
                    A01[2]=fma2(G01,Y2,A01[2]); B01[2]=fma2(G10,Y2,B01[2]);
                    A23[2]=fma2(G23,Y2,A23[2]); B23[2]=fma2(G32,Y2,B23[2]);
                    A01[3]=fma2(G01,Y3,A01[3]); B01[3]=fma2(G10,Y3,B01[3]);
                    A23[3]=fma2(G23,Y3,A23[3]); B23[3]=fma2(G32,Y3,B23[3]);
                    C01 = fma2(G01, y8d, C01);  C23 = fma2(G23, y8d, C23);
                }
            }
            // Mp[kk][p], kk=(s*4+r)*32+c(=lane): descrambled scalar stores
            #pragma unroll
            for (int j = 0; j < 4; j++){
                float a0,a1,b0,b1,c0,c1,d0,d1;
                unpack2(A01[j], a0, a1);   // a0=M[r0][2j]  a1=M[r1][2j+1]
                unpack2(B01[j], b0, b1);   // b0=M[r1][2j]  b1=M[r0][2j+1]
                unpack2(A23[j], c0, c1);   // c0=M[r2][2j]  c1=M[r3][2j+1]
                unpack2(B23[j], d0, d1);   // d0=M[r3][2j]  d1=M[r2][2j+1]
                sts32(Mp + (((2*j  )*4+0)*32 + lane)*MPS + p, a0);
                sts32(Mp + (((2*j  )*4+1)*32 + lane)*MPS + p, b0);
                sts32(Mp + (((2*j  )*4+2)*32 + lane)*MPS + p, c0);
                sts32(Mp + (((2*j  )*4+3)*32 + lane)*MPS + p, d0);
                sts32(Mp + (((2*j+1)*4+0)*32 + lane)*MPS + p, b1);
                sts32(Mp + (((2*j+1)*4+1)*32 + lane)*MPS + p, a1);
                sts32(Mp + (((2*j+1)*4+2)*32 + lane)*MPS + p, d1);
                sts32(Mp + (((2*j+1)*4+3)*32 + lane)*MPS + p, c1);
            }
            {
                float e0,e1,e2,e3;
                unpack2(C01, e0, e1);
                unpack2(C23, e2, e3);
                sts32(Mp + ((8*4+0)*32 + lane)*MPS + p, e0);
                sts32(Mp + ((8*4+1)*32 + lane)*MPS + p, e1);
                sts32(Mp + ((8*4+2)*32 + lane)*MPS + p, e2);
                sts32(Mp + ((8*4+3)*32 + lane)*MPS + p, e3);
            }
            __syncwarp();
        }
        __syncthreads();   // Mp complete

        // ================= Phase B: k-split GEMM, p-paired + swap =================
        // accP[i][u]=(out[pE_i][d2u],out[pO_i][d2u+1]); accQ[i][u]=(out[pO_i][d2u],out[pE_i][d2u+1])
        u64 accP[2][4], accQ[2][4];
        #pragma unroll
        for (int a = 0; a < 2; a++)
            #pragma unroll
            for (int b = 0; b < 4; b++){ accP[a][b]=0ull; accQ[a][b]=0ull; }

        const int kb = w*KPW;
        const ulonglong2* wq = ((const ulonglong2*)g_wlin) + dg*2;  // + k*8 (+1)
        ulonglong2 pf0[3], pf1[3];
        #pragma unroll
        for (int i = 0; i < 3; i++){
            pf0[i] = __ldg(wq + (long)(kb+i)*8);
            pf1[i] = __ldg(wq + (long)(kb+i)*8 + 1);
        }
        #pragma unroll 3
        for (int kk = 0; kk < KPW; kk++){
            const int k = kb + kk;
            const int slot = kk % 3;
            const ulonglong2 wa = pf0[slot];    // wa.x=(w d0,d1) wa.y=(d2,d3)
            const ulonglong2 wb = pf1[slot];    // wb.x=(d4,d5)  wb.y=(d6,d7)
            if (kk + 3 < KPW){
                pf0[slot] = __ldg(wq + (long)(k+3)*8);
                pf1[slot] = __ldg(wq + (long)(k+3)*8 + 1);
            }
            const float* mr = Mp + k*MPS + pg*4;
            u64 m01 = lds64(mr);       // (m_p0, m_p1)
            u64 m23 = lds64(mr + 2);   // (m_p2, m_p3)
            u64 m10 = swap2(m01);
            u64 m32 = swap2(m23);
            accP[0][0]=fma2(m01, wa.x, accP[0][0]); accQ[0][0]=fma2(m10, wa.x, accQ[0][0]);
            accP[0][1]=fma2(m01, wa.y, accP[0][1]); accQ[0][1]=fma2(m10, wa.y, accQ[0][1]);
            accP[0][2]=fma2(m01, wb.x, accP[0][2]); accQ[0][2]=fma2(m10, wb.x, accQ[0][2]);
            accP[0][3]=fma2(m01, wb.y, accP[0][3]); accQ[0][3]=fma2(m10, wb.y, accQ[0][3]);
            accP[1][0]=fma2(m23, wa.x, accP[1][0]); accQ[1][0]=fma2(m32, wa.x, accQ[1][0]);
            accP[1][1]=fma2(m23, wa.y, accP[1][1]); accQ[1][1]=fma2(m32, wa.y, accQ[1][1]);
            accP[1][2]=fma2(m23, wb.x, accP[1][2]); accQ[1][2]=fma2(m32, wb.x, accQ[1][2]);
            accP[1][3]=fma2(m23, wb.y, accP[1][3]); accQ[1][3]=fma2(m32, wb.y, accQ[1][3]);
        }
        __syncthreads();   // all Mp reads done before redd (alias) writes

        // partial store with descramble: slot [pi][dd] = (out[p][d2dd], out[p][d2dd+1])
        {
            u64* slotp = redd + (u64)(w*32 + lane)*17;
            #pragma unroll
            for (int i = 0; i < 2; i++){
                #pragma unroll
                for (int u = 0; u < 4; u++){
                    float Pa,Pb,Qa,Qb;
                    unpack2(accP[i][u], Pa, Pb);   // Pa=pE,d2u  Pb=pO,d2u+1
                    unpack2(accQ[i][u], Qa, Qb);   // Qa=pO,d2u  Qb=pE,d2u+1
                    sts64(slotp + (2*i  )*4 + u, pack2(Pa, Qb));
                    sts64(slotp + (2*i+1)*4 + u, pack2(Qa, Pb));
                }
            }
        }
        __syncthreads();

        // reduce 16 k-slices
        {
            const int rw = tid >> 5;           // 0..15 = pi*4+dd
            const int rl = tid & 31;           // producer lane
            const int pi = rw >> 2, dd = rw & 3;
            const int dgp = rl >> 3, pgp = rl & 7;
            const u64* base = redd + rl*17 + rw;
            u64 s = lds64(base);
            #pragma unroll
            for (int ks = 1; ks < 16; ks++)
                s = add2(s, lds64(base + ks*544));
            float lo, hi; unpack2(s, lo, hi);
            const int p = pgp*4 + pi;
            const int d = dgp*8 + dd*2;
            float* o = out + ((long)(n*DOUT + d))*BPTS + bb0 + p;
            o[0]    = lo;
            o[BPTS] = hi;
        }
        __syncthreads();   // protect redd (=Mp) before next iter's Phase A
    }
}

// ---------------- launch ----------------
extern "C" void kernel_launch(void* const* d_in, const int* in_sizes, int n_in,
                              void* d_out, int out_size)
{
    const float* input  = (const float*)d_in[0];
    const float* coords = (const float*)d_in[1];
    const float* rmask  = (const float*)d_in[2];
    const float* W      = (const float*)d_in[3];
    const int*   nbrs   = (const int*)d_in[4];
    float* out = (float*)d_out;

    (void)in_sizes; (void)n_in; (void)out_size;

    prep_all<<<1168, 256>>>(input, W);

    int dev = 0; cudaGetDevice(&dev);
    int smcount = 148;
    cudaDeviceGetAttribute(&smcount, cudaDevAttrMultiProcessorCount, dev);

    size_t shmem = (size_t)SM_FLOATS * sizeof(float);   // 183296 B
    cudaFuncSetAttribute(se3_main, cudaFuncAttributeMaxDynamicSharedMemorySize, (int)shmem);
    se3_main<<<smcount, THREADS, shmem>>>(coords, rmask, nbrs, out);
}

// round 12
// speedup vs baseline: 1.8364x; 1.4778x over previous
#include <cuda_runtime.h>

#define NN 4
#define BPTS 8192
#define CIN 32
#define DOUT 32
#define ANB 32
#define NBAS 36
#define TOTAL 32768
#define PPI 32
#define THREADS 512
#define WARPS 16
#define NITER (TOTAL/PPI)
#define KK 1152
#define SP 1156            // MpT row stride: 1156 mod 32 == 4 -> conflict-free both ways

typedef unsigned long long u64;
typedef unsigned int u32;

__device__ float g_inputT[NN*BPTS*CIN];       // (n,b,c)
__device__ float g_wfrag[4*144*32*2];          // B-fragments: [dtile][kstep][lane][2], tf32-rounded

// ---------------- f32x2 helpers ----------------
__device__ __forceinline__ u64 pack2(float x, float y){
    u64 r; asm("mov.b64 %0,{%1,%2};" : "=l"(r) : "f"(x), "f"(y)); return r;
}
__device__ __forceinline__ void unpack2(u64 v, float& x, float& y){
    asm("mov.b64 {%0,%1},%2;" : "=f"(x), "=f"(y) : "l"(v));
}
__device__ __forceinline__ u64 fma2(u64 a, u64 b, u64 c){
    u64 d; asm("fma.rn.f32x2 %0,%1,%2,%3;" : "=l"(d) : "l"(a), "l"(b), "l"(c)); return d;
}
__device__ __forceinline__ u64 mul2(u64 a, u64 b){
    u64 d; asm("mul.rn.f32x2 %0,%1,%2;" : "=l"(d) : "l"(a), "l"(b)); return d;
}
__device__ __forceinline__ float lds32(const float* p){
    float v; unsigned s = (unsigned)__cvta_generic_to_shared(p);
    asm volatile("ld.shared.f32 %0,[%1];" : "=f"(v) : "r"(s)); return v;
}
__device__ __forceinline__ u32 lds32u(const float* p){
    u32 v; unsigned s = (unsigned)__cvta_generic_to_shared(p);
    asm volatile("ld.shared.b32 %0,[%1];" : "=r"(v) : "r"(s)); return v;
}
__device__ __forceinline__ void sts32(float* p, float v){
    unsigned s = (unsigned)__cvta_generic_to_shared(p);
    asm volatile("st.shared.f32 [%0],%1;" :: "r"(s), "f"(v));
}
__device__ __forceinline__ u64 lds64(const void* p){
    u64 v; unsigned s = (unsigned)__cvta_generic_to_shared(p);
    asm volatile("ld.shared.b64 %0,[%1];" : "=l"(v) : "r"(s)); return v;
}
__device__ __forceinline__ void sts64(void* p, u64 v){
    unsigned s = (unsigned)__cvta_generic_to_shared(p);
    asm volatile("st.shared.b64 [%0],%1;" :: "r"(s), "l"(v));
}
__device__ __forceinline__ float tf32r(float x){
    float y; asm("cvt.rna.tf32.f32 %0,%1;" : "=f"(y) : "f"(x)); return y;
}
__device__ __forceinline__ void mma_tf32(float& d0, float& d1, float& d2, float& d3,
                                         u32 a0, u32 a1, u32 a2, u32 a3, u32 b0, u32 b1){
    asm volatile(
        "mma.sync.aligned.m16n8k8.row.col.f32.tf32.tf32.f32 "
        "{%0,%1,%2,%3}, {%4,%5,%6,%7}, {%8,%9}, {%0,%1,%2,%3};"
        : "+f"(d0), "+f"(d1), "+f"(d2), "+f"(d3)
        : "r"(a0), "r"(a1), "r"(a2), "r"(a3), "r"(b0), "r"(b1));
}

// ---------------- fused prep ----------------
// blocks [0,1024): transpose input; [1024,1168): pack W B-fragments (tf32-rounded)
__global__ void prep_all(const float* __restrict__ in, const float* __restrict__ W){
    const int bx = blockIdx.x;
    const int tid = threadIdx.x;           // 256
    if (bx < 1024){
        __shared__ float t[32][33];
        const int n  = bx >> 8;
        const int b0 = (bx & 255) * 32;
        const int tx = tid & 31, ty = tid >> 5;
        #pragma unroll
        for (int i = ty; i < 32; i += 8)
            t[i][tx] = in[(n*CIN + i)*BPTS + b0 + tx];
        __syncthreads();
        #pragma unroll
        for (int i = ty; i < 32; i += 8)
            g_inputT[(n*BPTS + b0 + i)*CIN + tx] = t[tx][i];
    } else {
        int t = (bx - 1024)*256 + tid;     // 36864 entries
        if (t < 4*144*32*2){
            int reg  = t & 1;
            int lane = (t >> 1) & 31;
            int rest = t >> 6;
            int kstep = rest % 144;
            int dtile = rest / 144;
            int g  = lane >> 2;            // d offset in tile
            int tt = lane & 3;             // k offset
            int kk = kstep*8 + tt + reg*4; // kk = (s*4+r)*32 + c
            int c   = kk & 31;
            int s4r = kk >> 5;
            int r = s4r & 3, s = s4r >> 2;
            int d = dtile*8 + g;
            float v = W[(d*CIN + c)*NBAS + r*9 + s];
            g_wfrag[t] = tf32r(v);
        }
    }
}

// ---------------- main ----------------
// smem floats:
//   geomP : 6 u64 fields x 512 = 6144   (rb01,rb23,(y0,y1),(y2,y3),(y4,y5),(y6,y7))
//   geomY8: 512
//   MpT   : 32 x 1156 = 36992           (tf32-rounded fp32, [p][kk])
//   redd  : 512 threads x 5 = 2560
// total 46208 f = 184832 B. No aliasing -> only 2 __syncthreads per iteration.
#define SM_GP   0
#define SM_Y8   6144
#define SM_MPT  6656
#define SM_RED  (6656 + 32*SP)
#define SM_FLOATS (SM_RED + 512*5)

__global__ void __launch_bounds__(THREADS, 1)
se3_main(const float* __restrict__ coords,
         const float* __restrict__ rmask,
         const int*   __restrict__ nbrs,
         float*       __restrict__ out)
{
    extern __shared__ float smem[];
    u64*   geomP  = (u64*)(smem + SM_GP);    // [q*512 + row]
    float* geomY8 = smem + SM_Y8;            // [row]
    float* MpT    = smem + SM_MPT;           // [p*SP + kk]
    float* redd   = smem + SM_RED;           // [(w*32+lane)*5 + i]

    const int tid  = threadIdx.x;
    const int w    = tid >> 5;               // 0..15
    const int lane = tid & 31;

    for (int grp = blockIdx.x; grp < NITER; grp += gridDim.x) {
        const int flatbase = grp*PPI;
        const int n   = flatbase >> 13;
        const int bb0 = flatbase & (BPTS-1);

        // ================= Phase A: 2 points per warp (R7 math) =================
        #pragma unroll 1
        for (int sub = 0; sub < 2; sub++){
            const int p = w*2 + sub;
            const int flat = flatbase + p;

            // geometry, lane = neighbor a
            const int nb_idx = flat*ANB + lane;
            const int jn  = nbrs[nb_idx];
            const float msk = rmask[nb_idx];
            const float* cc = coords + (long)flat*3;
            const float c0x = cc[0], c0y = cc[1], c0z = cc[2];
            const float* cj = coords + ((long)(n*BPTS + jn))*3;
            const float dx = cj[0]-c0x, dy = cj[1]-c0y, dz = cj[2]-c0z;
            const float r  = sqrtf(dx*dx + dy*dy + dz*dz);
            const float inv = __fdividef(1.0f, r + 1e-8f);
            const float ux = dx*inv, uy = dy*inv, uz = dz*inv;
            const float y0 = 0.28209479f;
            const float y1 = 0.48860251f*ux, y2 = 0.48860251f*uy, y3 = 0.48860251f*uz;
            const float y4 = 1.09254843f*ux*uy, y5 = 1.09254843f*uy*uz;
            const float y6 = 0.31539157f*(3.0f*uz*uz - 1.0f);
            const float y7 = 1.09254843f*ux*uz;
            const float y8 = 0.54627421f*(ux*ux - uy*uy);
            float rb0, rb1, rb2, rb3;
            {
                float t0 = (r - 0.5f)*2.0f, t1 = (r - 1.0f)*2.0f;
                float t2 = (r - 1.5f)*2.0f, t3 = (r - 2.0f)*2.0f;
                rb0 = msk*__expf(-t0*t0); rb1 = msk*__expf(-t1*t1);
                rb2 = msk*__expf(-t2*t2); rb3 = msk*__expf(-t3*t3);
            }
            const int row = w*32 + lane;
            sts64(geomP + 0*512 + row, pack2(rb0, rb1));
            sts64(geomP + 1*512 + row, pack2(rb2, rb3));
            sts64(geomP + 2*512 + row, pack2(y0, y1));
            sts64(geomP + 3*512 + row, pack2(y2, y3));
            sts64(geomP + 4*512 + row, pack2(y4, y5));
            sts64(geomP + 5*512 + row, pack2(y6, y7));
            sts32(geomY8 + row, y8);
            __syncwarp();

            // feature gather (lane = channel c), prefetch depth 8
            const float* inrow = g_inputT + (((long)n << 13) * CIN) + lane;
            float fp[8];
            #pragma unroll
            for (int q = 0; q < 8; q++){
                int jq = __shfl_sync(0xffffffffu, jn, q);
                fp[q] = __ldg(inrow + (long)jq*CIN);
            }
            u64 M01[9], M23[9];
            #pragma unroll
            for (int s = 0; s < 9; s++){ M01[s] = 0ull; M23[s] = 0ull; }

            #pragma unroll
            for (int a8 = 0; a8 < 32; a8 += 8){
                #pragma unroll
                for (int q = 0; q < 8; q++){
                    const int a = a8 + q;
                    const int row2 = w*32 + a;
                    u64 rb01 = lds64(geomP + 0*512 + row2);
                    u64 rb23 = lds64(geomP + 1*512 + row2);
                    u64 y01  = lds64(geomP + 2*512 + row2);
                    u64 y23  = lds64(geomP + 3*512 + row2);
                    u64 y45  = lds64(geomP + 4*512 + row2);
                    u64 y67  = lds64(geomP + 5*512 + row2);
                    float y8v = lds32(geomY8 + row2);
                    const float f = fp[q];
                    if (a8 + 8 < 32){
                        int jq = __shfl_sync(0xffffffffu, jn, a + 8);
                        fp[q] = __ldg(inrow + (long)jq*CIN);
                    }
                    u64 f2 = pack2(f, f);
                    u64 frb01 = mul2(f2, rb01);
                    u64 frb23 = mul2(f2, rb23);
                    float t0,t1,t2,t3,t4,t5,t6,t7;
                    unpack2(y01, t0, t1); unpack2(y23, t2, t3);
                    unpack2(y45, t4, t5); unpack2(y67, t6, t7);
                    u64 yd[9];
                    yd[0]=pack2(t0,t0); yd[1]=pack2(t1,t1); yd[2]=pack2(t2,t2);
                    yd[3]=pack2(t3,t3); yd[4]=pack2(t4,t4); yd[5]=pack2(t5,t5);
                    yd[6]=pack2(t6,t6); yd[7]=pack2(t7,t7); yd[8]=pack2(y8v,y8v);
                    #pragma unroll
                    for (int s = 0; s < 9; s++){
                        M01[s] = fma2(frb01, yd[s], M01[s]);
                        M23[s] = fma2(frb23, yd[s], M23[s]);
                    }
                }
            }
            // MpT[p][kk], kk=(s*4+r)*32+c(=lane); tf32-rounded; banks == lane (conflict-free)
            {
                float* base = MpT + p*SP + lane;
                #pragma unroll
                for (int s = 0; s < 9; s++){
                    float a0,a1,a2,a3;
                    unpack2(M01[s], a0, a1);
                    unpack2(M23[s], a2, a3);
                    sts32(base + s*128 +  0, tf32r(a0));
                    sts32(base + s*128 + 32, tf32r(a1));
                    sts32(base + s*128 + 64, tf32r(a2));
                    sts32(base + s*128 + 96, tf32r(a3));
                }
            }
            __syncwarp();
        }
        __syncthreads();   // (b1) MpT complete

        // ================= Phase B: tensor-core GEMM (m16n8k8 tf32) =================
        // warp -> combo = w>>1 (ptile = combo>>2, dtile = combo&3), khalf = w&1
        {
            const int combo = w >> 1;
            const int khalf = w & 1;
            const int ptile = combo >> 2;
            const int dtile = combo & 3;
            const int g  = lane >> 2;
            const int tt = lane & 3;
            const float* arow = MpT + (ptile*16 + g)*SP + khalf*576 + tt;
            const uint2* wf = ((const uint2*)g_wfrag) + (dtile*144 + khalf*72)*32 + lane;

            float d0 = 0.f, d1 = 0.f, d2 = 0.f, d3 = 0.f;
            uint2 wc = __ldg(wf);
            uint2 wn = __ldg(wf + 32);
            #pragma unroll
            for (int st = 0; st < 72; st++){
                u32 a0 = lds32u(arow + st*8);
                u32 a1 = lds32u(arow + st*8 + 8*SP);
                u32 a2 = lds32u(arow + st*8 + 4);
                u32 a3 = lds32u(arow + st*8 + 8*SP + 4);
                uint2 wcur = wc;
                wc = wn;
                if (st + 2 < 72) wn = __ldg(wf + (st+2)*32);
                mma_tf32(d0, d1, d2, d3, a0, a1, a2, a3, wcur.x, wcur.y);
            }
            float* rs = redd + (w*32 + lane)*5;
            sts32(rs + 0, d0);
            sts32(rs + 1, d1);
            sts32(rs + 2, d2);
            sts32(rs + 3, d3);
        }
        __syncthreads();   // (b2) redd complete

        // ================= reduce k-halves + store =================
        #pragma unroll
        for (int half = 0; half < 2; half++){
            const int f = tid + half*512;
            const int combo2 = f >> 7;
            const int rem = f & 127;
            const int lp = rem >> 2;
            const int i  = rem & 3;
            float v = lds32(redd + ((combo2*2  )*32 + lp)*5 + i)
                    + lds32(redd + ((combo2*2+1)*32 + lp)*5 + i);
            const int pt = combo2 >> 2, dt = combo2 & 3;
            const int gg = lp >> 2, tq = lp & 3;
            const int p = pt*16 + gg + (i >> 1)*8;
            const int d = dt*8 + tq*2 + (i & 1);
            out[((long)(n*DOUT + d))*BPTS + bb0 + p] = v;
        }
        // no further barrier needed: reduce reads precede next iteration's b1,
        // and redd writes occur only after b1.
    }
}

// ---------------- launch ----------------
extern "C" void kernel_launch(void* const* d_in, const int* in_sizes, int n_in,
                              void* d_out, int out_size)
{
    const float* input  = (const float*)d_in[0];
    const float* coords = (const float*)d_in[1];
    const float* rmask  = (const float*)d_in[2];
    const float* W      = (const float*)d_in[3];
    const int*   nbrs   = (const int*)d_in[4];
    float* out = (float*)d_out;

    (void)in_sizes; (void)n_in; (void)out_size;

    prep_all<<<1168, 256>>>(input, W);

    int dev = 0; cudaGetDevice(&dev);
    int smcount = 148;
    cudaDeviceGetAttribute(&smcount, cudaDevAttrMultiProcessorCount, dev);

    size_t shmem = (size_t)SM_FLOATS * sizeof(float);   // 184832 B
    cudaFuncSetAttribute(se3_main, cudaFuncAttributeMaxDynamicSharedMemorySize, (int)shmem);
    se3_main<<<smcount, THREADS, shmem>>>(coords, rmask, nbrs, out);
}

// round 13
// speedup vs baseline: 2.2146x; 1.2059x over previous
#include <cuda_runtime.h>

#define NN 4
#define BPTS 8192
#define CIN 32
#define DOUT 32
#define ANB 32
#define NBAS 36
#define TOTAL 32768
#define PPI 32
#define THREADS 512
#define WARPS 16
#define NITER (TOTAL/PPI)
#define KK 1152
#define SP 1156            // MpT row stride: == 4 mod 32, even
#define BSW 1296           // per-warp basis buffer: 36 sr-rows * 36 ld

typedef unsigned long long u64;
typedef unsigned int u32;

__device__ float g_inputT[NN*BPTS*CIN];       // (n,b,c), tf32-rounded
__device__ float g_wfrag[4*144*32*2];          // B-frags [dtile][kstep][lane][2], kk' = c*36+sr

// ---------------- helpers ----------------
__device__ __forceinline__ u64 pack2(float x, float y){
    u64 r; asm("mov.b64 %0,{%1,%2};" : "=l"(r) : "f"(x), "f"(y)); return r;
}
__device__ __forceinline__ float lds32(const float* p){
    float v; unsigned s = (unsigned)__cvta_generic_to_shared(p);
    asm volatile("ld.shared.f32 %0,[%1];" : "=f"(v) : "r"(s)); return v;
}
__device__ __forceinline__ u32 lds32u(const float* p){
    u32 v; unsigned s = (unsigned)__cvta_generic_to_shared(p);
    asm volatile("ld.shared.b32 %0,[%1];" : "=r"(v) : "r"(s)); return v;
}
__device__ __forceinline__ void sts32(float* p, float v){
    unsigned s = (unsigned)__cvta_generic_to_shared(p);
    asm volatile("st.shared.f32 [%0],%1;" :: "r"(s), "f"(v));
}
__device__ __forceinline__ void sts64(void* p, u64 v){
    unsigned s = (unsigned)__cvta_generic_to_shared(p);
    asm volatile("st.shared.b64 [%0],%1;" :: "r"(s), "l"(v));
}
__device__ __forceinline__ float tf32r(float x){
    float y; asm("cvt.rna.tf32.f32 %0,%1;" : "=f"(y) : "f"(x)); return y;
}
__device__ __forceinline__ void mma_tf32(float& d0, float& d1, float& d2, float& d3,
                                         u32 a0, u32 a1, u32 a2, u32 a3, u32 b0, u32 b1){
    asm volatile(
        "mma.sync.aligned.m16n8k8.row.col.f32.tf32.tf32.f32 "
        "{%0,%1,%2,%3}, {%4,%5,%6,%7}, {%8,%9}, {%0,%1,%2,%3};"
        : "+f"(d0), "+f"(d1), "+f"(d2), "+f"(d3)
        : "r"(a0), "r"(a1), "r"(a2), "r"(a3), "r"(b0), "r"(b1));
}

// ---------------- fused prep ----------------
__global__ void prep_all(const float* __restrict__ in, const float* __restrict__ W){
    const int bx = blockIdx.x;
    const int tid = threadIdx.x;           // 256
    if (bx < 1024){
        __shared__ float t[32][33];
        const int n  = bx >> 8;
        const int b0 = (bx & 255) * 32;
        const int tx = tid & 31, ty = tid >> 5;
        #pragma unroll
        for (int i = ty; i < 32; i += 8)
            t[i][tx] = in[(n*CIN + i)*BPTS + b0 + tx];
        __syncthreads();
        #pragma unroll
        for (int i = ty; i < 32; i += 8)
            g_inputT[(n*BPTS + b0 + i)*CIN + tx] = tf32r(t[tx][i]);   // pre-round feat
    } else {
        int t = (bx - 1024)*256 + tid;     // 36864 entries
        if (t < 4*144*32*2){
            int reg  = t & 1;
            int lane = (t >> 1) & 31;
            int rest = t >> 6;
            int kstep = rest % 144;
            int dtile = rest / 144;
            int g  = lane >> 2;
            int tt = lane & 3;
            int kkp = kstep*8 + tt + reg*4;   // kk' = c*36 + sr  (c-major)
            int c  = kkp / 36;
            int sr = kkp % 36;
            int r = sr & 3, s = sr >> 2;
            int d = dtile*8 + g;
            g_wfrag[t] = tf32r(W[(d*CIN + c)*NBAS + r*9 + s]);
        }
    }
}

// ---------------- main ----------------
// smem floats: Bs 16 warps * 1296 = 20736 | MpT 32*1156 = 36992  -> 230912 B
// redd (16w*32l*9 = 4608 f) ALIASES Bs (barrier-ordered).
#define SM_BS   0
#define SM_MPT  (WARPS*BSW)
#define SM_FLOATS (SM_MPT + 32*SP)

__global__ void __launch_bounds__(THREADS, 1)
se3_main(const float* __restrict__ coords,
         const float* __restrict__ rmask,
         const int*   __restrict__ nbrs,
         float*       __restrict__ out)
{
    extern __shared__ float smem[];
    float* BsAll = smem + SM_BS;             // [w][sr*36 + a]
    float* MpT   = smem + SM_MPT;            // [p*SP + kk']  kk' = c*36 + sr
    float* redd  = smem + SM_BS;             // alias of Bs, barrier-ordered

    const int tid  = threadIdx.x;
    const int w    = tid >> 5;               // 0..15
    const int lane = tid & 31;
    const int g    = lane >> 2;              // 0..7
    const int tt   = lane & 3;               // 0..3

    float* BsW = BsAll + w*BSW;

    for (int grp = blockIdx.x; grp < NITER; grp += gridDim.x) {
        const int flatbase = grp*PPI;
        const int n   = flatbase >> 13;
        const int bb0 = flatbase & (BPTS-1);
        const float* fbase = g_inputT + (((long)n << 13) * CIN);

        // ================= Phase A: 2 points per warp, tensor-core M =================
        #pragma unroll 1
        for (int sub = 0; sub < 2; sub++){
            const int p = w*2 + sub;
            const int flat = flatbase + p;

            // ---- geometry + basis build (lane = neighbor a) ----
            const int nb_idx = flat*ANB + lane;
            const int jn  = nbrs[nb_idx];
            const float msk = rmask[nb_idx];
            const float* cc = coords + (long)flat*3;
            const float c0x = cc[0], c0y = cc[1], c0z = cc[2];
            const float* cj = coords + ((long)(n*BPTS + jn))*3;
            const float dx = cj[0]-c0x, dy = cj[1]-c0y, dz = cj[2]-c0z;
            const float r  = sqrtf(dx*dx + dy*dy + dz*dz);
            const float inv = __fdividef(1.0f, r + 1e-8f);
            const float ux = dx*inv, uy = dy*inv, uz = dz*inv;
            float yv[9];
            yv[0] = 0.28209479f;
            yv[1] = 0.48860251f*ux; yv[2] = 0.48860251f*uy; yv[3] = 0.48860251f*uz;
            yv[4] = 1.09254843f*ux*uy; yv[5] = 1.09254843f*uy*uz;
            yv[6] = 0.31539157f*(3.0f*uz*uz - 1.0f);
            yv[7] = 1.09254843f*ux*uz;
            yv[8] = 0.54627421f*(ux*ux - uy*uy);
            float rb[4];
            {
                float t0 = (r - 0.5f)*2.0f, t1 = (r - 1.0f)*2.0f;
                float t2 = (r - 1.5f)*2.0f, t3 = (r - 2.0f)*2.0f;
                rb[0] = msk*__expf(-t0*t0); rb[1] = msk*__expf(-t1*t1);
                rb[2] = msk*__expf(-t2*t2); rb[3] = msk*__expf(-t3*t3);
            }
            // Bs[sr][a]: sr = s*4 + r; lane-distinct stride-1 stores
            #pragma unroll
            for (int s = 0; s < 9; s++){
                #pragma unroll
                for (int rr = 0; rr < 4; rr++)
                    sts32(BsW + (s*4 + rr)*36 + lane, tf32r(rb[rr]*yv[s]));
            }
            __syncwarp();

            // ---- M = feat^T * basis via 40 MMAs (m=c 32, n=sr 40, k=a 32) ----
            float acc[2][5][4];
            #pragma unroll
            for (int mt = 0; mt < 2; mt++)
                #pragma unroll
                for (int nt = 0; nt < 5; nt++)
                    #pragma unroll
                    for (int q = 0; q < 4; q++) acc[mt][nt][q] = 0.f;

            #pragma unroll
            for (int ks = 0; ks < 4; ks++){
                int jA = __shfl_sync(0xffffffffu, jn, ks*8 + tt);
                int jB = __shfl_sync(0xffffffffu, jn, ks*8 + tt + 4);
                const float* rowA = fbase + (long)jA*CIN;
                const float* rowB = fbase + (long)jB*CIN;
                #pragma unroll
                for (int mt = 0; mt < 2; mt++){
                    const int c0 = mt*16 + g;
                    u32 a0 = __float_as_uint(__ldg(rowA + c0));
                    u32 a1 = __float_as_uint(__ldg(rowA + c0 + 8));
                    u32 a2 = __float_as_uint(__ldg(rowB + c0));
                    u32 a3 = __float_as_uint(__ldg(rowB + c0 + 8));
                    #pragma unroll
                    for (int nt = 0; nt < 5; nt++){
                        const float* bp = BsW + (nt*8 + g)*36 + ks*8 + tt;
                        u32 b0 = lds32u(bp);
                        u32 b1 = lds32u(bp + 4);
                        mma_tf32(acc[mt][nt][0], acc[mt][nt][1], acc[mt][nt][2], acc[mt][nt][3],
                                 a0, a1, a2, a3, b0, b1);
                    }
                }
            }
            // ---- D -> MpT[p][c*36+sr], tf32-rounded, sts64 pairs ----
            {
                float* mbase = MpT + p*SP;
                #pragma unroll
                for (int mt = 0; mt < 2; mt++){
                    const int c0 = mt*16 + g;
                    #pragma unroll
                    for (int nt = 0; nt < 5; nt++){
                        const int sr0 = nt*8 + 2*tt;
                        if (sr0 < 36){
                            float v0 = tf32r(acc[mt][nt][0]);
                            float v1 = tf32r(acc[mt][nt][1]);
                            float v2 = tf32r(acc[mt][nt][2]);
                            float v3 = tf32r(acc[mt][nt][3]);
                            sts64(mbase + c0*36 + sr0,      pack2(v0, v1));
                            sts64(mbase + (c0+8)*36 + sr0,  pack2(v2, v3));
                        }
                    }
                }
            }
            __syncwarp();
        }
        __syncthreads();   // (b1) MpT complete

        // ================= Phase B: out = MpT x W, warp = (dtile, kquarter) ===========
        {
            const int dtile = w & 3;
            const int kq    = w >> 2;
            const float* arow0 = MpT + g*SP + kq*288 + tt;
            const float* arow1 = arow0 + 16*SP;
            const uint2* wf = ((const uint2*)g_wfrag) + (dtile*144 + kq*36)*32 + lane;

            float accB[2][4];
            #pragma unroll
            for (int mt = 0; mt < 2; mt++)
                #pragma unroll
                for (int q = 0; q < 4; q++) accB[mt][q] = 0.f;

            uint2 wc = __ldg(wf);
            uint2 wn = __ldg(wf + 32);
            #pragma unroll
            for (int st = 0; st < 36; st++){
                u32 a0 = lds32u(arow0 + st*8);
                u32 a1 = lds32u(arow0 + st*8 + 8*SP);
                u32 a2 = lds32u(arow0 + st*8 + 4);
                u32 a3 = lds32u(arow0 + st*8 + 8*SP + 4);
                u32 c0 = lds32u(arow1 + st*8);
                u32 c1 = lds32u(arow1 + st*8 + 8*SP);
                u32 c2 = lds32u(arow1 + st*8 + 4);
                u32 c3 = lds32u(arow1 + st*8 + 8*SP + 4);
                uint2 wcur = wc;
                wc = wn;
                if (st + 2 < 36) wn = __ldg(wf + (st+2)*32);
                mma_tf32(accB[0][0], accB[0][1], accB[0][2], accB[0][3],
                         a0, a1, a2, a3, wcur.x, wcur.y);
                mma_tf32(accB[1][0], accB[1][1], accB[1][2], accB[1][3],
                         c0, c1, c2, c3, wcur.x, wcur.y);
            }
            __syncthreads();   // (b2a) all MpT reads done before redd (alias Bs) writes

            float* rs = redd + (w*32 + lane)*9;
            #pragma unroll
            for (int mt = 0; mt < 2; mt++)
                #pragma unroll
                for (int q = 0; q < 4; q++)
                    sts32(rs + mt*4 + q, accB[mt][q]);
        }
        __syncthreads();   // (b2) redd complete

        // ================= reduce 4 k-quarters + coalesced store =================
        #pragma unroll
        for (int half = 0; half < 2; half++){
            const int p = tid & 31;
            const int d = (tid >> 5) + half*16;
            const int L = ((p & 7) << 2) | ((d & 7) >> 1);
            const int i = ((p >> 4) << 2) + ((p & 8) ? 2 : 0) + (d & 1);
            const int dt = d >> 3;
            float v = 0.f;
            #pragma unroll
            for (int kq = 0; kq < 4; kq++)
                v += lds32(redd + ((kq*4 + dt)*32 + L)*9 + i);
            out[((long)(n*DOUT + d))*BPTS + bb0 + p] = v;
        }
        __syncthreads();   // (b3) redd reads done before next iter writes Bs (alias)
    }
}

// ---------------- launch ----------------
extern "C" void kernel_launch(void* const* d_in, const int* in_sizes, int n_in,
                              void* d_out, int out_size)
{
    const float* input  = (const float*)d_in[0];
    const float* coords = (const float*)d_in[1];
    const float* rmask  = (const float*)d_in[2];
    const float* W      = (const float*)d_in[3];
    const int*   nbrs   = (const int*)d_in[4];
    float* out = (float*)d_out;

    (void)in_sizes; (void)n_in; (void)out_size;

    prep_all<<<1168, 256>>>(input, W);

    int dev = 0; cudaGetDevice(&dev);
    int smcount = 148;
    cudaDeviceGetAttribute(&smcount, cudaDevAttrMultiProcessorCount, dev);

    size_t shmem = (size_t)SM_FLOATS * sizeof(float);   // 230912 B
    cudaFuncSetAttribute(se3_main, cudaFuncAttributeMaxDynamicSharedMemorySize, (int)shmem);
    se3_main<<<smcount, THREADS, shmem>>>(coords, rmask, nbrs, out);
}

// round 14
// speedup vs baseline: 2.3644x; 1.0677x over previous
#include <cuda_runtime.h>

#define NN 4
#define BPTS 8192
#define CIN 32
#define DOUT 32
#define ANB 32
#define NBAS 36
#define TOTAL 32768
#define PPI 32
#define THREADS 512
#define WARPS 16
#define NITER (TOTAL/PPI)
#define KK 1152
#define SP 1156            // MpT row stride: == 4 mod 32, even
#define BSW 1296           // per-warp basis buffer: 36 sr-rows * 36 ld

typedef unsigned long long u64;
typedef unsigned int u32;

__device__ float g_inputT[NN*BPTS*CIN];       // (n,b,c), tf32-rounded
__device__ float g_wfrag[4*144*32*2];          // B-frags [dtile][kstep][lane][2], kk' = c*36+sr

// ---------------- helpers ----------------
__device__ __forceinline__ u64 pack2(float x, float y){
    u64 r; asm("mov.b64 %0,{%1,%2};" : "=l"(r) : "f"(x), "f"(y)); return r;
}
__device__ __forceinline__ float lds32(const float* p){
    float v; unsigned s = (unsigned)__cvta_generic_to_shared(p);
    asm volatile("ld.shared.f32 %0,[%1];" : "=f"(v) : "r"(s)); return v;
}
__device__ __forceinline__ u32 lds32u(const float* p){
    u32 v; unsigned s = (unsigned)__cvta_generic_to_shared(p);
    asm volatile("ld.shared.b32 %0,[%1];" : "=r"(v) : "r"(s)); return v;
}
__device__ __forceinline__ void sts32(float* p, float v){
    unsigned s = (unsigned)__cvta_generic_to_shared(p);
    asm volatile("st.shared.f32 [%0],%1;" :: "r"(s), "f"(v));
}
__device__ __forceinline__ void sts64(void* p, u64 v){
    unsigned s = (unsigned)__cvta_generic_to_shared(p);
    asm volatile("st.shared.b64 [%0],%1;" :: "r"(s), "l"(v));
}
__device__ __forceinline__ float tf32r(float x){
    float y; asm("cvt.rna.tf32.f32 %0,%1;" : "=f"(y) : "f"(x)); return y;
}
__device__ __forceinline__ void mma_tf32(float& d0, float& d1, float& d2, float& d3,
                                         u32 a0, u32 a1, u32 a2, u32 a3, u32 b0, u32 b1){
    asm volatile(
        "mma.sync.aligned.m16n8k8.row.col.f32.tf32.tf32.f32 "
        "{%0,%1,%2,%3}, {%4,%5,%6,%7}, {%8,%9}, {%0,%1,%2,%3};"
        : "+f"(d0), "+f"(d1), "+f"(d2), "+f"(d3)
        : "r"(a0), "r"(a1), "r"(a2), "r"(a3), "r"(b0), "r"(b1));
}

// ---------------- fused prep ----------------
__global__ void prep_all(const float* __restrict__ in, const float* __restrict__ W){
    const int bx = blockIdx.x;
    const int tid = threadIdx.x;           // 256
    if (bx < 1024){
        __shared__ float t[32][33];
        const int n  = bx >> 8;
        const int b0 = (bx & 255) * 32;
        const int tx = tid & 31, ty = tid >> 5;
        #pragma unroll
        for (int i = ty; i < 32; i += 8)
            t[i][tx] = in[(n*CIN + i)*BPTS + b0 + tx];
        __syncthreads();
        #pragma unroll
        for (int i = ty; i < 32; i += 8)
            g_inputT[(n*BPTS + b0 + i)*CIN + tx] = tf32r(t[tx][i]);   // pre-round feat
    } else {
        int t = (bx - 1024)*256 + tid;     // 36864 entries
        if (t < 4*144*32*2){
            int reg  = t & 1;
            int lane = (t >> 1) & 31;
            int rest = t >> 6;
            int kstep = rest % 144;
            int dtile = rest / 144;
            int g  = lane >> 2;
            int tt = lane & 3;
            int kkp = kstep*8 + tt + reg*4;   // kk' = c*36 + sr  (c-major)
            int c  = kkp / 36;
            int sr = kkp % 36;
            int r = sr & 3, s = sr >> 2;
            int d = dtile*8 + g;
            g_wfrag[t] = tf32r(W[(d*CIN + c)*NBAS + r*9 + s]);
        }
    }
}

// ---------------- main ----------------
// smem floats: Bs 16 warps * 1296 = 20736 | MpT 32*1156 = 36992  -> 230912 B
// redd (16w*32l*17 = 8704 f) ALIASES Bs (barrier-ordered).
#define SM_BS   0
#define SM_MPT  (WARPS*BSW)
#define SM_FLOATS (SM_MPT + 32*SP)

__global__ void __launch_bounds__(THREADS, 1)
se3_main(const float* __restrict__ coords,
         const float* __restrict__ rmask,
         const int*   __restrict__ nbrs,
         float*       __restrict__ out)
{
    extern __shared__ float smem[];
    float* BsAll = smem + SM_BS;             // [w][sr*36 + a]
    float* MpT   = smem + SM_MPT;            // [p*SP + kk']  kk' = c*36 + sr
    float* redd  = smem + SM_BS;             // alias of Bs, barrier-ordered

    const int tid  = threadIdx.x;
    const int w    = tid >> 5;               // 0..15
    const int lane = tid & 31;
    const int g    = lane >> 2;              // 0..7
    const int tt   = lane & 3;               // 0..3

    float* BsW = BsAll + w*BSW;

    for (int grp = blockIdx.x; grp < NITER; grp += gridDim.x) {
        const int flatbase = grp*PPI;
        const int n   = flatbase >> 13;
        const int bb0 = flatbase & (BPTS-1);
        const float* fbase = g_inputT + (((long)n << 13) * CIN);

        // ================= Phase A: 2 points per warp, tensor-core M =================
        #pragma unroll 1
        for (int sub = 0; sub < 2; sub++){
            const int p = w*2 + sub;
            const int flat = flatbase + p;

            // ---- geometry + basis build (lane = neighbor a) ----
            const int nb_idx = flat*ANB + lane;
            const int jn  = nbrs[nb_idx];
            const float msk = rmask[nb_idx];
            const float* cc = coords + (long)flat*3;
            const float c0x = cc[0], c0y = cc[1], c0z = cc[2];
            const float* cj = coords + ((long)(n*BPTS + jn))*3;
            const float dx = cj[0]-c0x, dy = cj[1]-c0y, dz = cj[2]-c0z;
            const float r  = sqrtf(dx*dx + dy*dy + dz*dz);
            const float inv = __fdividef(1.0f, r + 1e-8f);
            const float ux = dx*inv, uy = dy*inv, uz = dz*inv;
            float yv[9];
            yv[0] = 0.28209479f;
            yv[1] = 0.48860251f*ux; yv[2] = 0.48860251f*uy; yv[3] = 0.48860251f*uz;
            yv[4] = 1.09254843f*ux*uy; yv[5] = 1.09254843f*uy*uz;
            yv[6] = 0.31539157f*(3.0f*uz*uz - 1.0f);
            yv[7] = 1.09254843f*ux*uz;
            yv[8] = 0.54627421f*(ux*ux - uy*uy);
            float rb[4];
            {
                float t0 = (r - 0.5f)*2.0f, t1 = (r - 1.0f)*2.0f;
                float t2 = (r - 1.5f)*2.0f, t3 = (r - 2.0f)*2.0f;
                rb[0] = msk*__expf(-t0*t0); rb[1] = msk*__expf(-t1*t1);
                rb[2] = msk*__expf(-t2*t2); rb[3] = msk*__expf(-t3*t3);
            }
            // Bs[sr][a]: sr = s*4 + r; lane-distinct stride-1 stores
            #pragma unroll
            for (int s = 0; s < 9; s++){
                #pragma unroll
                for (int rr = 0; rr < 4; rr++)
                    sts32(BsW + (s*4 + rr)*36 + lane, tf32r(rb[rr]*yv[s]));
            }
            __syncwarp();

            // ---- M = feat^T * basis via 40 MMAs (m=c 32, n=sr 40, k=a 32) ----
            float acc[2][5][4];
            #pragma unroll
            for (int mt = 0; mt < 2; mt++)
                #pragma unroll
                for (int nt = 0; nt < 5; nt++)
                    #pragma unroll
                    for (int q = 0; q < 4; q++) acc[mt][nt][q] = 0.f;

            #pragma unroll
            for (int ks = 0; ks < 4; ks++){
                int jA = __shfl_sync(0xffffffffu, jn, ks*8 + tt);
                int jB = __shfl_sync(0xffffffffu, jn, ks*8 + tt + 4);
                const float* rowA = fbase + (long)jA*CIN;
                const float* rowB = fbase + (long)jB*CIN;
                // hoisted B-fragment loads (shared across mt)
                u32 bb[5][2];
                #pragma unroll
                for (int nt = 0; nt < 5; nt++){
                    const float* bp = BsW + (nt*8 + g)*36 + ks*8 + tt;
                    bb[nt][0] = lds32u(bp);
                    bb[nt][1] = lds32u(bp + 4);
                }
                #pragma unroll
                for (int mt = 0; mt < 2; mt++){
                    const int c0 = mt*16 + g;
                    u32 a0 = __float_as_uint(__ldg(rowA + c0));
                    u32 a1 = __float_as_uint(__ldg(rowA + c0 + 8));
                    u32 a2 = __float_as_uint(__ldg(rowB + c0));
                    u32 a3 = __float_as_uint(__ldg(rowB + c0 + 8));
                    #pragma unroll
                    for (int nt = 0; nt < 5; nt++)
                        mma_tf32(acc[mt][nt][0], acc[mt][nt][1], acc[mt][nt][2], acc[mt][nt][3],
                                 a0, a1, a2, a3, bb[nt][0], bb[nt][1]);
                }
            }
            // ---- D -> MpT[p][c*36+sr], tf32-rounded, sts64 pairs ----
            {
                float* mbase = MpT + p*SP;
                #pragma unroll
                for (int mt = 0; mt < 2; mt++){
                    const int c0 = mt*16 + g;
                    #pragma unroll
                    for (int nt = 0; nt < 5; nt++){
                        const int sr0 = nt*8 + 2*tt;
                        if (sr0 < 36){
                            float v0 = tf32r(acc[mt][nt][0]);
                            float v1 = tf32r(acc[mt][nt][1]);
                            float v2 = tf32r(acc[mt][nt][2]);
                            float v3 = tf32r(acc[mt][nt][3]);
                            sts64(mbase + c0*36 + sr0,      pack2(v0, v1));
                            sts64(mbase + (c0+8)*36 + sr0,  pack2(v2, v3));
                        }
                    }
                }
            }
            __syncwarp();
        }
        __syncthreads();   // (b1) MpT complete; all Bs reads also done

        // ========= Phase B: warp = (ptile, kq); n=32 via 4 MMAs sharing A =========
        {
            const int pt = w >> 3;            // 0..1
            const int kq = w & 7;             // 0..7  (144 kk' each, 18 steps)
            const float* arow = MpT + (pt*16 + g)*SP + kq*144 + tt;
            const uint2* wf = ((const uint2*)g_wfrag) + (kq*18)*32 + lane;   // + nt*144*32 + st*32

            float accB[4][4];
            #pragma unroll
            for (int nt = 0; nt < 4; nt++)
                #pragma unroll
                for (int q = 0; q < 4; q++) accB[nt][q] = 0.f;

            uint2 wc[4], wn[4];
            #pragma unroll
            for (int nt = 0; nt < 4; nt++){
                wc[nt] = __ldg(wf + nt*144*32);
                wn[nt] = __ldg(wf + nt*144*32 + 32);
            }
            #pragma unroll
            for (int st = 0; st < 18; st++){
                u32 a0 = lds32u(arow + st*8);
                u32 a1 = lds32u(arow + st*8 + 8*SP);
                u32 a2 = lds32u(arow + st*8 + 4);
                u32 a3 = lds32u(arow + st*8 + 8*SP + 4);
                #pragma unroll
                for (int nt = 0; nt < 4; nt++){
                    uint2 wcur = wc[nt];
                    wc[nt] = wn[nt];
                    if (st + 2 < 18) wn[nt] = __ldg(wf + nt*144*32 + (st+2)*32);
                    mma_tf32(accB[nt][0], accB[nt][1], accB[nt][2], accB[nt][3],
                             a0, a1, a2, a3, wcur.x, wcur.y);
                }
            }
            // store partials: redd[(w*32+lane)*17 + nt*4 + q]
            float* rs = redd + (w*32 + lane)*17;
            #pragma unroll
            for (int nt = 0; nt < 4; nt++)
                #pragma unroll
                for (int q = 0; q < 4; q++)
                    sts32(rs + nt*4 + q, accB[nt][q]);
        }
        __syncthreads();   // (b2) redd complete

        // ================= reduce 8 k-slices + coalesced store =================
        #pragma unroll
        for (int half = 0; half < 2; half++){
            const int p = tid & 31;
            const int d = (tid >> 5) + half*16;
            const int pt = p >> 4;
            const int pp = p & 15;
            const int g2 = pp & 7;
            const int ihi = pp >> 3;
            const int nt = d >> 3;
            const int tq = (d & 7) >> 1;
            const int i  = ihi*2 + (d & 1);
            const int L  = g2*4 + tq;
            float v = 0.f;
            #pragma unroll
            for (int kq = 0; kq < 8; kq++)
                v += lds32(redd + ((pt*8 + kq)*32 + L)*17 + nt*4 + i);
            out[((long)(n*DOUT + d))*BPTS + bb0 + p] = v;
        }
        __syncthreads();   // (b3) redd reads done before next iter writes Bs (alias)
    }
}

// ---------------- launch ----------------
extern "C" void kernel_launch(void* const* d_in, const int* in_sizes, int n_in,
                              void* d_out, int out_size)
{
    const float* input  = (const float*)d_in[0];
    const float* coords = (const float*)d_in[1];
    const float* rmask  = (const float*)d_in[2];
    const float* W      = (const float*)d_in[3];
    const int*   nbrs   = (const int*)d_in[4];
    float* out = (float*)d_out;

    (void)in_sizes; (void)n_in; (void)out_size;

    prep_all<<<1168, 256>>>(input, W);

    int dev = 0; cudaGetDevice(&dev);
    int smcount = 148;
    cudaDeviceGetAttribute(&smcount, cudaDevAttrMultiProcessorCount, dev);

    size_t shmem = (size_t)SM_FLOATS * sizeof(float);   // 230912 B
    cudaFuncSetAttribute(se3_main, cudaFuncAttributeMaxDynamicSharedMemorySize, (int)shmem);
    se3_main<<<smcount, THREADS, shmem>>>(coords, rmask, nbrs, out);
}

// round 15
// speedup vs baseline: 2.4118x; 1.0200x over previous
#include <cuda_runtime.h>

#define NN 4
#define BPTS 8192
#define CIN 32
#define DOUT 32
#define ANB 32
#define NBAS 36
#define TOTAL 32768
#define PPI 16              // points per CTA iteration
#define THREADS 256
#define WARPS 8
#define NITER (TOTAL/PPI)   // 2048
#define KK 1152
#define SP 1156             // MpT row stride: == 4 mod 32, even
#define BSW 1296            // per-warp basis buffer: 36 sr-rows * 36 ld

typedef unsigned long long u64;
typedef unsigned int u32;

__device__ float g_inputT[NN*BPTS*CIN];       // (n,b,c), tf32-rounded
__device__ float g_wfrag[4*144*32*2];          // B-frags [dtile][kstep][lane][2], kk' = c*36+sr

// ---------------- helpers ----------------
__device__ __forceinline__ u64 pack2(float x, float y){
    u64 r; asm("mov.b64 %0,{%1,%2};" : "=l"(r) : "f"(x), "f"(y)); return r;
}
__device__ __forceinline__ float lds32(const float* p){
    float v; unsigned s = (unsigned)__cvta_generic_to_shared(p);
    asm volatile("ld.shared.f32 %0,[%1];" : "=f"(v) : "r"(s)); return v;
}
__device__ __forceinline__ u32 lds32u(const float* p){
    u32 v; unsigned s = (unsigned)__cvta_generic_to_shared(p);
    asm volatile("ld.shared.b32 %0,[%1];" : "=r"(v) : "r"(s)); return v;
}
__device__ __forceinline__ void sts32(float* p, float v){
    unsigned s = (unsigned)__cvta_generic_to_shared(p);
    asm volatile("st.shared.f32 [%0],%1;" :: "r"(s), "f"(v));
}
__device__ __forceinline__ void sts64(void* p, u64 v){
    unsigned s = (unsigned)__cvta_generic_to_shared(p);
    asm volatile("st.shared.b64 [%0],%1;" :: "r"(s), "l"(v));
}
__device__ __forceinline__ float tf32r(float x){
    float y; asm("cvt.rna.tf32.f32 %0,%1;" : "=f"(y) : "f"(x)); return y;
}
__device__ __forceinline__ void mma_tf32(float& d0, float& d1, float& d2, float& d3,
                                         u32 a0, u32 a1, u32 a2, u32 a3, u32 b0, u32 b1){
    asm volatile(
        "mma.sync.aligned.m16n8k8.row.col.f32.tf32.tf32.f32 "
        "{%0,%1,%2,%3}, {%4,%5,%6,%7}, {%8,%9}, {%0,%1,%2,%3};"
        : "+f"(d0), "+f"(d1), "+f"(d2), "+f"(d3)
        : "r"(a0), "r"(a1), "r"(a2), "r"(a3), "r"(b0), "r"(b1));
}

// ---------------- fused prep ----------------
__global__ void prep_all(const float* __restrict__ in, const float* __restrict__ W){
    const int bx = blockIdx.x;
    const int tid = threadIdx.x;           // 256
    if (bx < 1024){
        __shared__ float t[32][33];
        const int n  = bx >> 8;
        const int b0 = (bx & 255) * 32;
        const int tx = tid & 31, ty = tid >> 5;
        #pragma unroll
        for (int i = ty; i < 32; i += 8)
            t[i][tx] = in[(n*CIN + i)*BPTS + b0 + tx];
        __syncthreads();
        #pragma unroll
        for (int i = ty; i < 32; i += 8)
            g_inputT[(n*BPTS + b0 + i)*CIN + tx] = tf32r(t[tx][i]);
    } else {
        int t = (bx - 1024)*256 + tid;     // 36864 entries
        if (t < 4*144*32*2){
            int reg  = t & 1;
            int lane = (t >> 1) & 31;
            int rest = t >> 6;
            int kstep = rest % 144;
            int dtile = rest / 144;
            int g  = lane >> 2;
            int tt = lane & 3;
            int kkp = kstep*8 + tt + reg*4;   // kk' = c*36 + sr
            int c  = kkp / 36;
            int sr = kkp % 36;
            int r = sr & 3, s = sr >> 2;
            int d = dtile*8 + g;
            g_wfrag[t] = tf32r(W[(d*CIN + c)*NBAS + r*9 + s]);
        }
    }
}

// ---------------- main ----------------
// smem floats (per CTA): Bs 8 warps * 1296 = 10368 | MpT 16*1156 = 18496
// total 28864 f = 115456 B; 2 CTAs/SM (230912 B <= 228KB SM limit).
// redd (8w*32l*17 = 4352 f) ALIASES Bs (barrier-ordered).
#define SM_BS   0
#define SM_MPT  (WARPS*BSW)
#define SM_FLOATS (SM_MPT + PPI*SP)

__global__ void __launch_bounds__(THREADS, 2)
se3_main(const float* __restrict__ coords,
         const float* __restrict__ rmask,
         const int*   __restrict__ nbrs,
         float*       __restrict__ out)
{
    extern __shared__ float smem[];
    float* BsAll = smem + SM_BS;             // [w][sr*36 + a]
    float* MpT   = smem + SM_MPT;            // [p*SP + kk']  kk' = c*36 + sr
    float* redd  = smem + SM_BS;             // alias of Bs, barrier-ordered

    const int tid  = threadIdx.x;
    const int w    = tid >> 5;               // 0..7
    const int lane = tid & 31;
    const int g    = lane >> 2;              // 0..7
    const int tt   = lane & 3;               // 0..3

    float* BsW = BsAll + w*BSW;

    for (int grp = blockIdx.x; grp < NITER; grp += gridDim.x) {
        const int flatbase = grp*PPI;
        const int n   = flatbase >> 13;
        const int bb0 = flatbase & (BPTS-1);
        const float* fbase = g_inputT + (((long)n << 13) * CIN);

        // ================= Phase A: 2 points per warp, tensor-core M =================
        #pragma unroll 1
        for (int sub = 0; sub < 2; sub++){
            const int p = w*2 + sub;
            const int flat = flatbase + p;

            // ---- geometry + basis build (lane = neighbor a) ----
            const int nb_idx = flat*ANB + lane;
            const int jn  = nbrs[nb_idx];
            const float msk = rmask[nb_idx];
            const float* cc = coords + (long)flat*3;
            const float c0x = cc[0], c0y = cc[1], c0z = cc[2];
            const float* cj = coords + ((long)(n*BPTS + jn))*3;
            const float dx = cj[0]-c0x, dy = cj[1]-c0y, dz = cj[2]-c0z;
            const float r  = sqrtf(dx*dx + dy*dy + dz*dz);
            const float inv = __fdividef(1.0f, r + 1e-8f);
            const float ux = dx*inv, uy = dy*inv, uz = dz*inv;
            float yv[9];
            yv[0] = 0.28209479f;
            yv[1] = 0.48860251f*ux; yv[2] = 0.48860251f*uy; yv[3] = 0.48860251f*uz;
            yv[4] = 1.09254843f*ux*uy; yv[5] = 1.09254843f*uy*uz;
            yv[6] = 0.31539157f*(3.0f*uz*uz - 1.0f);
            yv[7] = 1.09254843f*ux*uz;
            yv[8] = 0.54627421f*(ux*ux - uy*uy);
            float rb[4];
            {
                float t0 = (r - 0.5f)*2.0f, t1 = (r - 1.0f)*2.0f;
                float t2 = (r - 1.5f)*2.0f, t3 = (r - 2.0f)*2.0f;
                rb[0] = msk*__expf(-t0*t0); rb[1] = msk*__expf(-t1*t1);
                rb[2] = msk*__expf(-t2*t2); rb[3] = msk*__expf(-t3*t3);
            }
            // Bs[sr][a]: lane-distinct stride-1 stores
            #pragma unroll
            for (int s = 0; s < 9; s++){
                #pragma unroll
                for (int rr = 0; rr < 4; rr++)
                    sts32(BsW + (s*4 + rr)*36 + lane, tf32r(rb[rr]*yv[s]));
            }
            __syncwarp();

            // ---- M = feat^T * basis via 40 MMAs (m=c 32, n=sr 40, k=a 32) ----
            float acc[2][5][4];
            #pragma unroll
            for (int mt = 0; mt < 2; mt++)
                #pragma unroll
                for (int nt = 0; nt < 5; nt++)
                    #pragma unroll
                    for (int q = 0; q < 4; q++) acc[mt][nt][q] = 0.f;

            #pragma unroll
            for (int ks = 0; ks < 4; ks++){
                int jA = __shfl_sync(0xffffffffu, jn, ks*8 + tt);
                int jB = __shfl_sync(0xffffffffu, jn, ks*8 + tt + 4);
                const float* rowA = fbase + (long)jA*CIN;
                const float* rowB = fbase + (long)jB*CIN;
                u32 bb[5][2];
                #pragma unroll
                for (int nt = 0; nt < 5; nt++){
                    const float* bp = BsW + (nt*8 + g)*36 + ks*8 + tt;
                    bb[nt][0] = lds32u(bp);
                    bb[nt][1] = lds32u(bp + 4);
                }
                #pragma unroll
                for (int mt = 0; mt < 2; mt++){
                    const int c0 = mt*16 + g;
                    u32 a0 = __float_as_uint(__ldg(rowA + c0));
                    u32 a1 = __float_as_uint(__ldg(rowA + c0 + 8));
                    u32 a2 = __float_as_uint(__ldg(rowB + c0));
                    u32 a3 = __float_as_uint(__ldg(rowB + c0 + 8));
                    #pragma unroll
                    for (int nt = 0; nt < 5; nt++)
                        mma_tf32(acc[mt][nt][0], acc[mt][nt][1], acc[mt][nt][2], acc[mt][nt][3],
                                 a0, a1, a2, a3, bb[nt][0], bb[nt][1]);
                }
            }
            // ---- D -> MpT[p][c*36+sr], tf32-rounded, sts64 pairs ----
            {
                float* mbase = MpT + p*SP;
                #pragma unroll
                for (int mt = 0; mt < 2; mt++){
                    const int c0 = mt*16 + g;
                    #pragma unroll
                    for (int nt = 0; nt < 5; nt++){
                        const int sr0 = nt*8 + 2*tt;
                        if (sr0 < 36){
                            float v0 = tf32r(acc[mt][nt][0]);
                            float v1 = tf32r(acc[mt][nt][1]);
                            float v2 = tf32r(acc[mt][nt][2]);
                            float v3 = tf32r(acc[mt][nt][3]);
                            sts64(mbase + c0*36 + sr0,      pack2(v0, v1));
                            sts64(mbase + (c0+8)*36 + sr0,  pack2(v2, v3));
                        }
                    }
                }
            }
            __syncwarp();
        }
        __syncthreads();   // (b1) MpT complete; all Bs reads also done

        // ========= Phase B: warp = kq (k-eighth); m16 (all p) x n32 via 4 MMAs =========
        {
            const int kq = w;                 // 0..7, 144 kk' each, 18 steps
            const float* arow = MpT + g*SP + kq*144 + tt;
            const uint2* wf = ((const uint2*)g_wfrag) + (kq*18)*32 + lane;   // + nt*144*32 + st*32

            float accB[4][4];
            #pragma unroll
            for (int nt = 0; nt < 4; nt++)
                #pragma unroll
                for (int q = 0; q < 4; q++) accB[nt][q] = 0.f;

            uint2 wc[4], wn[4];
            #pragma unroll
            for (int nt = 0; nt < 4; nt++){
                wc[nt] = __ldg(wf + nt*144*32);
                wn[nt] = __ldg(wf + nt*144*32 + 32);
            }
            #pragma unroll
            for (int st = 0; st < 18; st++){
                u32 a0 = lds32u(arow + st*8);
                u32 a1 = lds32u(arow + st*8 + 8*SP);
                u32 a2 = lds32u(arow + st*8 + 4);
                u32 a3 = lds32u(arow + st*8 + 8*SP + 4);
                #pragma unroll
                for (int nt = 0; nt < 4; nt++){
                    uint2 wcur = wc[nt];
                    wc[nt] = wn[nt];
                    if (st + 2 < 18) wn[nt] = __ldg(wf + nt*144*32 + (st+2)*32);
                    mma_tf32(accB[nt][0], accB[nt][1], accB[nt][2], accB[nt][3],
                             a0, a1, a2, a3, wcur.x, wcur.y);
                }
            }
            // store partials: redd[(kq*32+lane)*17 + nt*4 + q]
            float* rs = redd + (w*32 + lane)*17;
            #pragma unroll
            for (int nt = 0; nt < 4; nt++)
                #pragma unroll
                for (int q = 0; q < 4; q++)
                    sts32(rs + nt*4 + q, accB[nt][q]);
        }
        __syncthreads();   // (b2) redd complete

        // ================= reduce 8 k-slices + store =================
        // fragment map: p = g + (q>=2)*8, d = nt*8 + tt*2 + (q&1), lane L = g*4+tt
        #pragma unroll
        for (int half = 0; half < 2; half++){
            const int p = tid & 15;
            const int d = (tid >> 4) + half*16;
            const int g2  = p & 7;
            const int hi  = p >> 3;
            const int nt  = d >> 3;
            const int tq  = (d & 7) >> 1;
            const int q   = hi*2 + (d & 1);
            const int L   = g2*4 + tq;
            float v = 0.f;
            #pragma unroll
            for (int kq = 0; kq < 8; kq++)
                v += lds32(redd + (kq*32 + L)*17 + nt*4 + q);
            out[((long)(n*DOUT + d))*BPTS + bb0 + p] = v;
        }
        __syncthreads();   // (b3) redd reads done before next iter writes Bs (alias)
    }
}

// ---------------- launch ----------------
extern "C" void kernel_launch(void* const* d_in, const int* in_sizes, int n_in,
                              void* d_out, int out_size)
{
    const float* input  = (const float*)d_in[0];
    const float* coords = (const float*)d_in[1];
    const float* rmask  = (const float*)d_in[2];
    const float* W      = (const float*)d_in[3];
    const int*   nbrs   = (const int*)d_in[4];
    float* out = (float*)d_out;

    (void)in_sizes; (void)n_in; (void)out_size;

    prep_all<<<1168, 256>>>(input, W);

    int dev = 0; cudaGetDevice(&dev);
    int smcount = 148;
    cudaDeviceGetAttribute(&smcount, cudaDevAttrMultiProcessorCount, dev);

    size_t shmem = (size_t)SM_FLOATS * sizeof(float);   // 115456 B per CTA
    cudaFuncSetAttribute(se3_main, cudaFuncAttributeMaxDynamicSharedMemorySize, (int)shmem);
    se3_main<<<2*smcount, THREADS, shmem>>>(coords, rmask, nbrs, out);
}

// round 16
// speedup vs baseline: 2.4859x; 1.0307x over previous
#include <cuda_runtime.h>

#define NN 4
#define BPTS 8192
#define CIN 32
#define DOUT 32
#define ANB 32
#define NBAS 36
#define TOTAL 32768
#define PPI 16              // points per CTA iteration
#define THREADS 256
#define WARPS 8
#define NITER (TOTAL/PPI)   // 2048
#define KK 1152
#define SP 1156             // MpT row stride: == 4 mod 32, even
#define BSW 1296            // per-warp basis buffer: 36 sr-rows * 36 ld

typedef unsigned long long u64;
typedef unsigned int u32;

__device__ float g_inputT[NN*BPTS*CIN];       // (n,b,c), tf32-rounded
__device__ float g_wfrag[4*144*32*2];          // B-frags [dtile][kstep][lane][2], kk' = c*36+sr

// ---------------- helpers (pure asm only where required) ----------------
__device__ __forceinline__ float tf32r(float x){
    float y; asm("cvt.rna.tf32.f32 %0,%1;" : "=f"(y) : "f"(x)); return y;
}
__device__ __forceinline__ void mma_tf32(float& d0, float& d1, float& d2, float& d3,
                                         u32 a0, u32 a1, u32 a2, u32 a3, u32 b0, u32 b1){
    asm volatile(
        "mma.sync.aligned.m16n8k8.row.col.f32.tf32.tf32.f32 "
        "{%0,%1,%2,%3}, {%4,%5,%6,%7}, {%8,%9}, {%0,%1,%2,%3};"
        : "+f"(d0), "+f"(d1), "+f"(d2), "+f"(d3)
        : "r"(a0), "r"(a1), "r"(a2), "r"(a3), "r"(b0), "r"(b1));
}

// ---------------- fused prep ----------------
__global__ void prep_all(const float* __restrict__ in, const float* __restrict__ W){
    const int bx = blockIdx.x;
    const int tid = threadIdx.x;           // 256
    if (bx < 1024){
        __shared__ float t[32][33];
        const int n  = bx >> 8;
        const int b0 = (bx & 255) * 32;
        const int tx = tid & 31, ty = tid >> 5;
        #pragma unroll
        for (int i = ty; i < 32; i += 8)
            t[i][tx] = in[(n*CIN + i)*BPTS + b0 + tx];
        __syncthreads();
        #pragma unroll
        for (int i = ty; i < 32; i += 8)
            g_inputT[(n*BPTS + b0 + i)*CIN + tx] = tf32r(t[tx][i]);
    } else {
        int t = (bx - 1024)*256 + tid;     // 36864 entries
        if (t < 4*144*32*2){
            int reg  = t & 1;
            int lane = (t >> 1) & 31;
            int rest = t >> 6;
            int kstep = rest % 144;
            int dtile = rest / 144;
            int g  = lane >> 2;
            int tt = lane & 3;
            int kkp = kstep*8 + tt + reg*4;   // kk' = c*36 + sr
            int c  = kkp / 36;
            int sr = kkp % 36;
            int r = sr & 3, s = sr >> 2;
            int d = dtile*8 + g;
            g_wfrag[t] = tf32r(W[(d*CIN + c)*NBAS + r*9 + s]);
        }
    }
}

// ---------------- main ----------------
// smem floats (per CTA): Bs 8 warps * 1296 = 10368 | MpT 16*1156 = 18496
// total 28864 f = 115456 B; 2 CTAs/SM. redd (8w*32l*17 = 4352 f) ALIASES Bs.
#define SM_BS   0
#define SM_MPT  (WARPS*BSW)
#define SM_FLOATS (SM_MPT + PPI*SP)

__global__ void __launch_bounds__(THREADS, 2)
se3_main(const float* __restrict__ coords,
         const float* __restrict__ rmask,
         const int*   __restrict__ nbrs,
         float*       __restrict__ out)
{
    extern __shared__ float smem[];
    float* BsAll = smem + SM_BS;             // [w][sr*36 + a]
    float* MpT   = smem + SM_MPT;            // [p*SP + kk']  kk' = c*36 + sr
    float* redd  = smem + SM_BS;             // alias of Bs, barrier-ordered

    const int tid  = threadIdx.x;
    const int w    = tid >> 5;               // 0..7
    const int lane = tid & 31;
    const int g    = lane >> 2;              // 0..7
    const int tt   = lane & 3;               // 0..3

    float* BsW = BsAll + w*BSW;

    for (int grp = blockIdx.x; grp < NITER; grp += gridDim.x) {
        const int flatbase = grp*PPI;
        const int n   = flatbase >> 13;
        const int bb0 = flatbase & (BPTS-1);
        const float* fbase = g_inputT + (((long)n << 13) * CIN);

        // ================= Phase A: 2 points per warp, tensor-core M =================
        #pragma unroll 1
        for (int sub = 0; sub < 2; sub++){
            const int p = w*2 + sub;
            const int flat = flatbase + p;

            // ---- neighbor indices + EARLY feature prefetch (32 LDG, MLP batched) ----
            const int nb_idx = flat*ANB + lane;
            const int jn  = nbrs[nb_idx];
            const float msk = rmask[nb_idx];

            float fv[4][8];   // [ks][0..3: rowA c=g,g+8,g+16,g+24 ; 4..7: rowB same]
            #pragma unroll
            for (int ks = 0; ks < 4; ks++){
                int jA = __shfl_sync(0xffffffffu, jn, ks*8 + tt);
                int jB = __shfl_sync(0xffffffffu, jn, ks*8 + tt + 4);
                const float* rowA = fbase + (long)jA*CIN;
                const float* rowB = fbase + (long)jB*CIN;
                fv[ks][0] = __ldg(rowA + g);
                fv[ks][1] = __ldg(rowA + g + 8);
                fv[ks][2] = __ldg(rowA + g + 16);
                fv[ks][3] = __ldg(rowA + g + 24);
                fv[ks][4] = __ldg(rowB + g);
                fv[ks][5] = __ldg(rowB + g + 8);
                fv[ks][6] = __ldg(rowB + g + 16);
                fv[ks][7] = __ldg(rowB + g + 24);
            }

            // ---- geometry + basis build (overlaps the feature loads) ----
            const float* cc = coords + (long)flat*3;
            const float c0x = cc[0], c0y = cc[1], c0z = cc[2];
            const float* cj = coords + ((long)(n*BPTS + jn))*3;
            const float dx = cj[0]-c0x, dy = cj[1]-c0y, dz = cj[2]-c0z;
            const float r  = sqrtf(dx*dx + dy*dy + dz*dz);
            const float inv = __fdividef(1.0f, r + 1e-8f);
            const float ux = dx*inv, uy = dy*inv, uz = dz*inv;
            float yv[9];
            yv[0] = 0.28209479f;
            yv[1] = 0.48860251f*ux; yv[2] = 0.48860251f*uy; yv[3] = 0.48860251f*uz;
            yv[4] = 1.09254843f*ux*uy; yv[5] = 1.09254843f*uy*uz;
            yv[6] = 0.31539157f*(3.0f*uz*uz - 1.0f);
            yv[7] = 1.09254843f*ux*uz;
            yv[8] = 0.54627421f*(ux*ux - uy*uy);
            float rb[4];
            {
                float t0 = (r - 0.5f)*2.0f, t1 = (r - 1.0f)*2.0f;
                float t2 = (r - 1.5f)*2.0f, t3 = (r - 2.0f)*2.0f;
                rb[0] = msk*__expf(-t0*t0); rb[1] = msk*__expf(-t1*t1);
                rb[2] = msk*__expf(-t2*t2); rb[3] = msk*__expf(-t3*t3);
            }
            // Bs[sr][a]: lane-distinct stride-1 stores (plain -> schedulable)
            #pragma unroll
            for (int s = 0; s < 9; s++){
                #pragma unroll
                for (int rr = 0; rr < 4; rr++)
                    BsW[(s*4 + rr)*36 + lane] = tf32r(rb[rr]*yv[s]);
            }
            __syncwarp();

            // ---- M = feat^T * basis via 40 MMAs (m=c 32, n=sr 40, k=a 32) ----
            float acc[2][5][4];
            #pragma unroll
            for (int mt = 0; mt < 2; mt++)
                #pragma unroll
                for (int nt = 0; nt < 5; nt++)
                    #pragma unroll
                    for (int q = 0; q < 4; q++) acc[mt][nt][q] = 0.f;

            #pragma unroll
            for (int ks = 0; ks < 4; ks++){
                u32 bb[5][2];
                #pragma unroll
                for (int nt = 0; nt < 5; nt++){
                    const float* bp = BsW + (nt*8 + g)*36 + ks*8 + tt;
                    bb[nt][0] = __float_as_uint(bp[0]);
                    bb[nt][1] = __float_as_uint(bp[4]);
                }
                #pragma unroll
                for (int mt = 0; mt < 2; mt++){
                    u32 a0 = __float_as_uint(fv[ks][mt*2 + 0]);
                    u32 a1 = __float_as_uint(fv[ks][mt*2 + 1]);
                    u32 a2 = __float_as_uint(fv[ks][mt*2 + 4]);
                    u32 a3 = __float_as_uint(fv[ks][mt*2 + 5]);
                    #pragma unroll
                    for (int nt = 0; nt < 5; nt++)
                        mma_tf32(acc[mt][nt][0], acc[mt][nt][1], acc[mt][nt][2], acc[mt][nt][3],
                                 a0, a1, a2, a3, bb[nt][0], bb[nt][1]);
                }
            }
            // ---- D -> MpT[p][c*36+sr], tf32-rounded, float2 stores ----
            {
                float* mbase = MpT + p*SP;
                #pragma unroll
                for (int mt = 0; mt < 2; mt++){
                    const int c0 = mt*16 + g;
                    #pragma unroll
                    for (int nt = 0; nt < 5; nt++){
                        const int sr0 = nt*8 + 2*tt;
                        if (sr0 < 36){
                            *(float2*)(mbase + c0*36 + sr0) =
                                make_float2(tf32r(acc[mt][nt][0]), tf32r(acc[mt][nt][1]));
                            *(float2*)(mbase + (c0+8)*36 + sr0) =
                                make_float2(tf32r(acc[mt][nt][2]), tf32r(acc[mt][nt][3]));
                        }
                    }
                }
            }
            __syncwarp();
        }
        __syncthreads();   // (b1) MpT complete; all Bs reads also done

        // ========= Phase B: warp = kq (k-eighth); m16 (all p) x n32 via 4 MMAs =========
        {
            const int kq = w;                 // 0..7, 144 kk' each, 18 steps
            const float* arow = MpT + g*SP + kq*144 + tt;
            const uint2* wf = ((const uint2*)g_wfrag) + (kq*18)*32 + lane;

            float accB[4][4];
            #pragma unroll
            for (int nt = 0; nt < 4; nt++)
                #pragma unroll
                for (int q = 0; q < 4; q++) accB[nt][q] = 0.f;

            #pragma unroll
            for (int st = 0; st < 18; st++){
                u32 a0 = __float_as_uint(arow[st*8]);
                u32 a1 = __float_as_uint(arow[st*8 + 8*SP]);
                u32 a2 = __float_as_uint(arow[st*8 + 4]);
                u32 a3 = __float_as_uint(arow[st*8 + 8*SP + 4]);
                #pragma unroll
                for (int nt = 0; nt < 4; nt++){
                    uint2 wv = __ldg(wf + nt*144*32 + st*32);
                    mma_tf32(accB[nt][0], accB[nt][1], accB[nt][2], accB[nt][3],
                             a0, a1, a2, a3, wv.x, wv.y);
                }
            }
            float* rs = redd + (w*32 + lane)*17;
            #pragma unroll
            for (int nt = 0; nt < 4; nt++)
                #pragma unroll
                for (int q = 0; q < 4; q++)
                    rs[nt*4 + q] = accB[nt][q];
        }
        __syncthreads();   // (b2) redd complete

        // ================= reduce 8 k-slices + store =================
        // fragment map: p = g + (q>=2)*8, d = nt*8 + tt*2 + (q&1), lane L = g*4+tt
        #pragma unroll
        for (int half = 0; half < 2; half++){
            const int p = tid & 15;
            const int d = (tid >> 4) + half*16;
            const int g2  = p & 7;
            const int hi  = p >> 3;
            const int nt  = d >> 3;
            const int tq  = (d & 7) >> 1;
            const int q   = hi*2 + (d & 1);
            const int L   = g2*4 + tq;
            float v = 0.f;
            #pragma unroll
            for (int kq = 0; kq < 8; kq++)
                v += redd[(kq*32 + L)*17 + nt*4 + q];
            out[((long)(n*DOUT + d))*BPTS + bb0 + p] = v;
        }
        __syncthreads();   // (b3) redd reads done before next iter writes Bs (alias)
    }
}

// ---------------- launch ----------------
extern "C" void kernel_launch(void* const* d_in, const int* in_sizes, int n_in,
                              void* d_out, int out_size)
{
    const float* input  = (const float*)d_in[0];
    const float* coords = (const float*)d_in[1];
    const float* rmask  = (const float*)d_in[2];
    const float* W      = (const float*)d_in[3];
    const int*   nbrs   = (const int*)d_in[4];
    float* out = (float*)d_out;

    (void)in_sizes; (void)n_in; (void)out_size;

    prep_all<<<1168, 256>>>(input, W);

    int dev = 0; cudaGetDevice(&dev);
    int smcount = 148;
    cudaDeviceGetAttribute(&smcount, cudaDevAttrMultiProcessorCount, dev);

    size_t shmem = (size_t)SM_FLOATS * sizeof(float);   // 115456 B per CTA
    cudaFuncSetAttribute(se3_main, cudaFuncAttributeMaxDynamicSharedMemorySize, (int)shmem);
    se3_main<<<2*smcount, THREADS, shmem>>>(coords, rmask, nbrs, out);
}